// round 1
// baseline (speedup 1.0000x reference)
#include <cuda_runtime.h>
#include <cuda_bf16.h>
#include <mma.h>
#include <cstdint>

using namespace nvcuda;

#define N_MESH 40962
#define N_GRID 262144
#define N_EDGE 786432
#define DF 128
#define HDIM 256

// scratch for scatter-sum aggregation (device global: allocation-free)
__device__ float g_agg[(size_t)N_GRID * DF];

static __device__ __forceinline__ float totf(float x) { return wmma::__float_to_tf32(x); }

// shared memory layout (floats):
//   s0  : [0, 128*264)          A (ld 132 or 260) -> H (ld 264) -> Y (ld 132)
//   sB  : [128*264, +32*264)    B chunk (ld 264 for GEMM1, ld 132 for GEMM2)
#define LDA_E 132
#define LDA_N 260
#define LDH   264
#define LDB1  264
#define LDB2  132
#define LDY   132
#define SMEM_FLOATS (128*264 + 32*264)

// ---------------------------------------------------------------------------
__global__ void zero_agg_kernel() {
    size_t i = (size_t)blockIdx.x * blockDim.x + threadIdx.x;
    float4* p = reinterpret_cast<float4*>(g_agg);
    const size_t n = (size_t)N_GRID * DF / 4;
    if (i < n) p[i] = make_float4(0.f, 0.f, 0.f, 0.f);
}

// ---------------------------------------------------------------------------
// Edge MLP: cat(efeat, mesh[src], grid[dst]) [128,384] -> H[128,256] silu
//           -> Y[128,128] -> +b2 -> LN -> atomicAdd into g_agg[dst]
__global__ void __launch_bounds__(512, 1)
edge_kernel(const float* __restrict__ efeat, const float* __restrict__ gridf,
            const float* __restrict__ mesh, const int* __restrict__ src,
            const int* __restrict__ dst,
            const float* __restrict__ W1, const float* __restrict__ b1,
            const float* __restrict__ W2, const float* __restrict__ b2,
            const float* __restrict__ gam, const float* __restrict__ bet)
{
    extern __shared__ float sm[];
    float* s0 = sm;
    float* sB = sm + 128 * 264;

    const int tid  = threadIdx.x;
    const int warp = tid >> 5, lane = tid & 31;
    const int wm = warp >> 2, wn = warp & 3;
    const int e0 = blockIdx.x * 128;

    // ---------------- GEMM1: [128,384] @ W1[384,256] ----------------
    wmma::fragment<wmma::accumulator, 16, 16, 8, float> acc[2][4];
    #pragma unroll
    for (int i = 0; i < 2; i++)
        #pragma unroll
        for (int j = 0; j < 4; j++) wmma::fill_fragment(acc[i][j], 0.f);

    float4 stg[4];
    // preload W1 chunk 0 (rows 0..31, 256 cols)
    #pragma unroll
    for (int i = 0; i < 4; i++) {
        int f = tid + 512 * i; int r = f >> 6, c4 = f & 63;
        stg[i] = *reinterpret_cast<const float4*>(&W1[(size_t)r * 256 + c4 * 4]);
    }

    #pragma unroll 1
    for (int part = 0; part < 3; part++) {
        __syncthreads();  // previous part's MMAs done before overwriting A
        // gather A part: 128 rows x 128 cols, tf32-rounded
        {
            int r  = tid >> 2;
            int c0 = (tid & 3) * 32;
            const float* sp;
            if (part == 0)      sp = efeat + (size_t)(e0 + r) * DF;
            else if (part == 1) sp = mesh  + (size_t)__ldg(&src[e0 + r]) * DF;
            else                sp = gridf + (size_t)__ldg(&dst[e0 + r]) * DF;
            #pragma unroll
            for (int i = 0; i < 8; i++) {
                float4 v = *reinterpret_cast<const float4*>(sp + c0 + i * 4);
                float* d = &s0[r * LDA_E + c0 + i * 4];
                d[0] = totf(v.x); d[1] = totf(v.y); d[2] = totf(v.z); d[3] = totf(v.w);
            }
        }
        #pragma unroll 1
        for (int kc = 0; kc < 4; kc++) {
            __syncthreads();  // prior chunk's MMAs done before overwriting B
            #pragma unroll
            for (int i = 0; i < 4; i++) {
                int f = tid + 512 * i; int r = f >> 6, c4 = f & 63;
                float* d = &sB[r * LDB1 + c4 * 4];
                d[0] = totf(stg[i].x); d[1] = totf(stg[i].y);
                d[2] = totf(stg[i].z); d[3] = totf(stg[i].w);
            }
            __syncthreads();
            int next = part * 4 + kc + 1;
            if (next < 12) {
                int kg = next * 32;
                #pragma unroll
                for (int i = 0; i < 4; i++) {
                    int f = tid + 512 * i; int r = f >> 6, c4 = f & 63;
                    stg[i] = *reinterpret_cast<const float4*>(&W1[(size_t)(kg + r) * 256 + c4 * 4]);
                }
            }
            #pragma unroll
            for (int kk = 0; kk < 32; kk += 8) {
                wmma::fragment<wmma::matrix_a, 16, 16, 8, wmma::precision::tf32, wmma::row_major> a0, a1;
                wmma::load_matrix_sync(a0, &s0[(wm * 32)      * LDA_E + kc * 32 + kk], LDA_E);
                wmma::load_matrix_sync(a1, &s0[(wm * 32 + 16) * LDA_E + kc * 32 + kk], LDA_E);
                #pragma unroll
                for (int j = 0; j < 4; j++) {
                    wmma::fragment<wmma::matrix_b, 16, 16, 8, wmma::precision::tf32, wmma::row_major> b;
                    wmma::load_matrix_sync(b, &sB[kk * LDB1 + wn * 64 + j * 16], LDB1);
                    wmma::mma_sync(acc[0][j], a0, b, acc[0][j]);
                    wmma::mma_sync(acc[1][j], a1, b, acc[1][j]);
                }
            }
        }
    }
    __syncthreads();
    // store acc -> H (A region dead)
    #pragma unroll
    for (int i = 0; i < 2; i++)
        #pragma unroll
        for (int j = 0; j < 4; j++)
            wmma::store_matrix_sync(&s0[(wm * 32 + i * 16) * LDH + wn * 64 + j * 16],
                                    acc[i][j], LDH, wmma::mem_row_major);
    __syncthreads();
    // bias + SiLU (in place, tf32-rounded), vectorized
    #pragma unroll
    for (int i = 0; i < 16; i++) {
        int f = tid + 512 * i;              // 0..8191 float4s
        int r = f >> 6, c4 = f & 63;
        float* p = &s0[r * LDH + c4 * 4];
        float4 v = *reinterpret_cast<float4*>(p);
        float4 bb = *reinterpret_cast<const float4*>(&b1[c4 * 4]);
        float h0 = v.x + bb.x, h1 = v.y + bb.y, h2 = v.z + bb.z, h3 = v.w + bb.w;
        p[0] = totf(h0 / (1.f + __expf(-h0)));
        p[1] = totf(h1 / (1.f + __expf(-h1)));
        p[2] = totf(h2 / (1.f + __expf(-h2)));
        p[3] = totf(h3 / (1.f + __expf(-h3)));
    }

    // ---------------- GEMM2: H[128,256] @ W2[256,128] ----------------
    wmma::fragment<wmma::accumulator, 16, 16, 8, float> acc2[2][2];
    #pragma unroll
    for (int i = 0; i < 2; i++)
        #pragma unroll
        for (int j = 0; j < 2; j++) wmma::fill_fragment(acc2[i][j], 0.f);

    float4 st2[2];
    #pragma unroll
    for (int i = 0; i < 2; i++) {
        int f = tid + 512 * i; int r = f >> 5, c4 = f & 31;
        st2[i] = *reinterpret_cast<const float4*>(&W2[(size_t)r * 128 + c4 * 4]);
    }
    #pragma unroll 1
    for (int kc = 0; kc < 8; kc++) {
        __syncthreads();
        #pragma unroll
        for (int i = 0; i < 2; i++) {
            int f = tid + 512 * i; int r = f >> 5, c4 = f & 31;
            float* d = &sB[r * LDB2 + c4 * 4];
            d[0] = totf(st2[i].x); d[1] = totf(st2[i].y);
            d[2] = totf(st2[i].z); d[3] = totf(st2[i].w);
        }
        __syncthreads();
        if (kc + 1 < 8) {
            int kg = (kc + 1) * 32;
            #pragma unroll
            for (int i = 0; i < 2; i++) {
                int f = tid + 512 * i; int r = f >> 5, c4 = f & 31;
                st2[i] = *reinterpret_cast<const float4*>(&W2[(size_t)(kg + r) * 128 + c4 * 4]);
            }
        }
        #pragma unroll
        for (int kk = 0; kk < 32; kk += 8) {
            wmma::fragment<wmma::matrix_a, 16, 16, 8, wmma::precision::tf32, wmma::row_major> a0, a1;
            wmma::load_matrix_sync(a0, &s0[(wm * 32)      * LDH + kc * 32 + kk], LDH);
            wmma::load_matrix_sync(a1, &s0[(wm * 32 + 16) * LDH + kc * 32 + kk], LDH);
            #pragma unroll
            for (int j = 0; j < 2; j++) {
                wmma::fragment<wmma::matrix_b, 16, 16, 8, wmma::precision::tf32, wmma::row_major> b;
                wmma::load_matrix_sync(b, &sB[kk * LDB2 + wn * 32 + j * 16], LDB2);
                wmma::mma_sync(acc2[0][j], a0, b, acc2[0][j]);
                wmma::mma_sync(acc2[1][j], a1, b, acc2[1][j]);
            }
        }
    }
    __syncthreads();
    // store Y (H region dead)
    #pragma unroll
    for (int i = 0; i < 2; i++)
        #pragma unroll
        for (int j = 0; j < 2; j++)
            wmma::store_matrix_sync(&s0[(wm * 32 + i * 16) * LDY + wn * 32 + j * 16],
                                    acc2[i][j], LDY, wmma::mem_row_major);
    __syncthreads();

    // ---------------- +b2, LayerNorm, scatter atomicAdd ----------------
    #pragma unroll 1
    for (int i = 0; i < 8; i++) {
        int row = warp * 8 + i;
        float v[4], sum = 0.f, sq = 0.f;
        #pragma unroll
        for (int j = 0; j < 4; j++) {
            int c = lane + 32 * j;
            v[j] = s0[row * LDY + c] + __ldg(&b2[c]);
            sum += v[j]; sq += v[j] * v[j];
        }
        #pragma unroll
        for (int o = 16; o > 0; o >>= 1) {
            sum += __shfl_xor_sync(0xFFFFFFFFu, sum, o);
            sq  += __shfl_xor_sync(0xFFFFFFFFu, sq,  o);
        }
        float mean = sum * (1.f / 128.f);
        float var  = sq  * (1.f / 128.f) - mean * mean;
        float rstd = rsqrtf(var + 1e-5f);
        int dn = __ldg(&dst[e0 + row]);
        float* ap = g_agg + (size_t)dn * DF;
        #pragma unroll
        for (int j = 0; j < 4; j++) {
            int c = lane + 32 * j;
            float o = (v[j] - mean) * rstd * __ldg(&gam[c]) + __ldg(&bet[c]);
            atomicAdd(ap + c, o);
        }
    }
}

// ---------------------------------------------------------------------------
// Node MLP: cat(agg, grid) [128,256] -> H[128,256] silu -> Y[128,128]
//           -> +b2 -> LN -> *g+beta -> +grid residual -> out
__global__ void __launch_bounds__(512, 1)
node_kernel(const float* __restrict__ gridf,
            const float* __restrict__ W1, const float* __restrict__ b1,
            const float* __restrict__ W2, const float* __restrict__ b2,
            const float* __restrict__ gam, const float* __restrict__ bet,
            float* __restrict__ out)
{
    extern __shared__ float sm[];
    float* s0 = sm;
    float* sB = sm + 128 * 264;

    const int tid  = threadIdx.x;
    const int warp = tid >> 5, lane = tid & 31;
    const int wm = warp >> 2, wn = warp & 3;
    const int n0 = blockIdx.x * 128;

    // gather A: [128, 256] = [agg | grid]
    {
        int r  = tid >> 2;
        int c0 = (tid & 3) * 32;
        const float* ap = g_agg + (size_t)(n0 + r) * DF;
        const float* gp = gridf + (size_t)(n0 + r) * DF;
        #pragma unroll
        for (int i = 0; i < 8; i++) {
            float4 v = *reinterpret_cast<const float4*>(ap + c0 + i * 4);
            float* d = &s0[r * LDA_N + c0 + i * 4];
            d[0] = totf(v.x); d[1] = totf(v.y); d[2] = totf(v.z); d[3] = totf(v.w);
            float4 w = *reinterpret_cast<const float4*>(gp + c0 + i * 4);
            float* e = &s0[r * LDA_N + 128 + c0 + i * 4];
            e[0] = totf(w.x); e[1] = totf(w.y); e[2] = totf(w.z); e[3] = totf(w.w);
        }
    }

    // GEMM1: [128,256] @ W1[256,256]
    wmma::fragment<wmma::accumulator, 16, 16, 8, float> acc[2][4];
    #pragma unroll
    for (int i = 0; i < 2; i++)
        #pragma unroll
        for (int j = 0; j < 4; j++) wmma::fill_fragment(acc[i][j], 0.f);

    float4 stg[4];
    #pragma unroll
    for (int i = 0; i < 4; i++) {
        int f = tid + 512 * i; int r = f >> 6, c4 = f & 63;
        stg[i] = *reinterpret_cast<const float4*>(&W1[(size_t)r * 256 + c4 * 4]);
    }
    #pragma unroll 1
    for (int kc = 0; kc < 8; kc++) {
        __syncthreads();
        #pragma unroll
        for (int i = 0; i < 4; i++) {
            int f = tid + 512 * i; int r = f >> 6, c4 = f & 63;
            float* d = &sB[r * LDB1 + c4 * 4];
            d[0] = totf(stg[i].x); d[1] = totf(stg[i].y);
            d[2] = totf(stg[i].z); d[3] = totf(stg[i].w);
        }
        __syncthreads();
        if (kc + 1 < 8) {
            int kg = (kc + 1) * 32;
            #pragma unroll
            for (int i = 0; i < 4; i++) {
                int f = tid + 512 * i; int r = f >> 6, c4 = f & 63;
                stg[i] = *reinterpret_cast<const float4*>(&W1[(size_t)(kg + r) * 256 + c4 * 4]);
            }
        }
        #pragma unroll
        for (int kk = 0; kk < 32; kk += 8) {
            wmma::fragment<wmma::matrix_a, 16, 16, 8, wmma::precision::tf32, wmma::row_major> a0, a1;
            wmma::load_matrix_sync(a0, &s0[(wm * 32)      * LDA_N + kc * 32 + kk], LDA_N);
            wmma::load_matrix_sync(a1, &s0[(wm * 32 + 16) * LDA_N + kc * 32 + kk], LDA_N);
            #pragma unroll
            for (int j = 0; j < 4; j++) {
                wmma::fragment<wmma::matrix_b, 16, 16, 8, wmma::precision::tf32, wmma::row_major> b;
                wmma::load_matrix_sync(b, &sB[kk * LDB1 + wn * 64 + j * 16], LDB1);
                wmma::mma_sync(acc[0][j], a0, b, acc[0][j]);
                wmma::mma_sync(acc[1][j], a1, b, acc[1][j]);
            }
        }
    }
    __syncthreads();
    #pragma unroll
    for (int i = 0; i < 2; i++)
        #pragma unroll
        for (int j = 0; j < 4; j++)
            wmma::store_matrix_sync(&s0[(wm * 32 + i * 16) * LDH + wn * 64 + j * 16],
                                    acc[i][j], LDH, wmma::mem_row_major);
    __syncthreads();
    #pragma unroll
    for (int i = 0; i < 16; i++) {
        int f = tid + 512 * i;
        int r = f >> 6, c4 = f & 63;
        float* p = &s0[r * LDH + c4 * 4];
        float4 v = *reinterpret_cast<float4*>(p);
        float4 bb = *reinterpret_cast<const float4*>(&b1[c4 * 4]);
        float h0 = v.x + bb.x, h1 = v.y + bb.y, h2 = v.z + bb.z, h3 = v.w + bb.w;
        p[0] = totf(h0 / (1.f + __expf(-h0)));
        p[1] = totf(h1 / (1.f + __expf(-h1)));
        p[2] = totf(h2 / (1.f + __expf(-h2)));
        p[3] = totf(h3 / (1.f + __expf(-h3)));
    }

    // GEMM2: H[128,256] @ W2[256,128]
    wmma::fragment<wmma::accumulator, 16, 16, 8, float> acc2[2][2];
    #pragma unroll
    for (int i = 0; i < 2; i++)
        #pragma unroll
        for (int j = 0; j < 2; j++) wmma::fill_fragment(acc2[i][j], 0.f);

    float4 st2[2];
    #pragma unroll
    for (int i = 0; i < 2; i++) {
        int f = tid + 512 * i; int r = f >> 5, c4 = f & 31;
        st2[i] = *reinterpret_cast<const float4*>(&W2[(size_t)r * 128 + c4 * 4]);
    }
    #pragma unroll 1
    for (int kc = 0; kc < 8; kc++) {
        __syncthreads();
        #pragma unroll
        for (int i = 0; i < 2; i++) {
            int f = tid + 512 * i; int r = f >> 5, c4 = f & 31;
            float* d = &sB[r * LDB2 + c4 * 4];
            d[0] = totf(st2[i].x); d[1] = totf(st2[i].y);
            d[2] = totf(st2[i].z); d[3] = totf(st2[i].w);
        }
        __syncthreads();
        if (kc + 1 < 8) {
            int kg = (kc + 1) * 32;
            #pragma unroll
            for (int i = 0; i < 2; i++) {
                int f = tid + 512 * i; int r = f >> 5, c4 = f & 31;
                st2[i] = *reinterpret_cast<const float4*>(&W2[(size_t)(kg + r) * 128 + c4 * 4]);
            }
        }
        #pragma unroll
        for (int kk = 0; kk < 32; kk += 8) {
            wmma::fragment<wmma::matrix_a, 16, 16, 8, wmma::precision::tf32, wmma::row_major> a0, a1;
            wmma::load_matrix_sync(a0, &s0[(wm * 32)      * LDH + kc * 32 + kk], LDH);
            wmma::load_matrix_sync(a1, &s0[(wm * 32 + 16) * LDH + kc * 32 + kk], LDH);
            #pragma unroll
            for (int j = 0; j < 2; j++) {
                wmma::fragment<wmma::matrix_b, 16, 16, 8, wmma::precision::tf32, wmma::row_major> b;
                wmma::load_matrix_sync(b, &sB[kk * LDB2 + wn * 32 + j * 16], LDB2);
                wmma::mma_sync(acc2[0][j], a0, b, acc2[0][j]);
                wmma::mma_sync(acc2[1][j], a1, b, acc2[1][j]);
            }
        }
    }
    __syncthreads();
    #pragma unroll
    for (int i = 0; i < 2; i++)
        #pragma unroll
        for (int j = 0; j < 2; j++)
            wmma::store_matrix_sync(&s0[(wm * 32 + i * 16) * LDY + wn * 32 + j * 16],
                                    acc2[i][j], LDY, wmma::mem_row_major);
    __syncthreads();

    // +b2, LN, affine, +residual, write out
    #pragma unroll 1
    for (int i = 0; i < 8; i++) {
        int row = warp * 8 + i;
        float v[4], sum = 0.f, sq = 0.f;
        #pragma unroll
        for (int j = 0; j < 4; j++) {
            int c = lane + 32 * j;
            v[j] = s0[row * LDY + c] + __ldg(&b2[c]);
            sum += v[j]; sq += v[j] * v[j];
        }
        #pragma unroll
        for (int o = 16; o > 0; o >>= 1) {
            sum += __shfl_xor_sync(0xFFFFFFFFu, sum, o);
            sq  += __shfl_xor_sync(0xFFFFFFFFu, sq,  o);
        }
        float mean = sum * (1.f / 128.f);
        float var  = sq  * (1.f / 128.f) - mean * mean;
        float rstd = rsqrtf(var + 1e-5f);
        size_t base = (size_t)(n0 + row) * DF;
        #pragma unroll
        for (int j = 0; j < 4; j++) {
            int c = lane + 32 * j;
            float o = (v[j] - mean) * rstd * __ldg(&gam[c]) + __ldg(&bet[c]);
            out[base + c] = o + __ldg(&gridf[base + c]);
        }
    }
}

// ---------------------------------------------------------------------------
extern "C" void kernel_launch(void* const* d_in, const int* in_sizes, int n_in,
                              void* d_out, int out_size)
{
    const float* efeat = (const float*)d_in[0];
    const float* gridf = (const float*)d_in[1];
    const float* mesh  = (const float*)d_in[2];
    const int*   src   = (const int*)d_in[3];
    const int*   dst   = (const int*)d_in[4];
    const float* eW1   = (const float*)d_in[5];
    const float* eb1   = (const float*)d_in[6];
    const float* eW2   = (const float*)d_in[7];
    const float* eb2   = (const float*)d_in[8];
    const float* eg    = (const float*)d_in[9];
    const float* ebeta = (const float*)d_in[10];
    const float* nW1   = (const float*)d_in[11];
    const float* nb1   = (const float*)d_in[12];
    const float* nW2   = (const float*)d_in[13];
    const float* nb2   = (const float*)d_in[14];
    const float* ng    = (const float*)d_in[15];
    const float* nbeta = (const float*)d_in[16];
    float* out = (float*)d_out;

    const size_t smem = SMEM_FLOATS * sizeof(float);  // 168960 bytes
    cudaFuncSetAttribute(edge_kernel, cudaFuncAttributeMaxDynamicSharedMemorySize, (int)smem);
    cudaFuncSetAttribute(node_kernel, cudaFuncAttributeMaxDynamicSharedMemorySize, (int)smem);

    zero_agg_kernel<<<8192, 1024>>>();
    edge_kernel<<<N_EDGE / 128, 512, smem>>>(efeat, gridf, mesh, src, dst,
                                             eW1, eb1, eW2, eb2, eg, ebeta);
    node_kernel<<<N_GRID / 128, 512, smem>>>(gridf, nW1, nb1, nW2, nb2, ng, nbeta, out);
}

// round 3
// speedup vs baseline: 1.0694x; 1.0694x over previous
#include <cuda_runtime.h>
#include <mma.h>
#include <cstdint>

using namespace nvcuda;

#define N_MESH 40962
#define N_GRID 262144
#define N_EDGE 786432

// ------------------------------ device scratch ------------------------------
__device__ float g_agg[(size_t)N_GRID * 128];
__device__ float g_W1e[384 * 256];   // eW1 [K][N], tf32-RN pre-rounded
__device__ float g_W2e[256 * 128];
__device__ float g_W1n[256 * 256];
__device__ float g_W2n[256 * 128];

// ------------------------------ smem layout (float offsets) -----------------
#define S_B1f  0            // 256
#define S_B2f  256          // 128
#define S_Gf   384          // 128
#define S_BTf  512          // 128
#define S_A0f  1024         // 2 x (128 x 36)   = 2 x 4608
#define S_B0f  10240        // 2 x (32 x 260)   = 2 x 8320
#define S_Hf   1024         // 128 x 260 = 33280 (overlaps dead A/B bufs)
#define S_B20f 34304        // 2 x (32 x 132)   = 2 x 4224
#define S_Yf   1024         // 128 x 132 (overlaps dead H)
#define SMEM_FLOATS 42752   // 171,008 bytes

#define LDA  36
#define LDB1 260
#define LDH  260
#define LDB2 132
#define LDY  132

// ------------------------------ helpers -------------------------------------
static __device__ __forceinline__ float totf(float x) { return wmma::__float_to_tf32(x); }

__device__ __forceinline__ uint32_t smem_u32(const void* p) {
    uint32_t a;
    asm("{ .reg .u64 t; cvta.to.shared.u64 t, %1; cvt.u32.u64 %0, t; }" : "=r"(a) : "l"(p));
    return a;
}
__device__ __forceinline__ void cpa16(uint32_t s, const void* g) {
    asm volatile("cp.async.cg.shared.global [%0], [%1], 16;" :: "r"(s), "l"(g) : "memory");
}
__device__ __forceinline__ void cp_commit() {
    asm volatile("cp.async.commit_group;" ::: "memory");
}
__device__ __forceinline__ void cp_wait0() {
    asm volatile("cp.async.wait_group 0;" ::: "memory");
}

// ------------------------------ prep kernels --------------------------------
__global__ void zero_agg_kernel() {
    size_t i = (size_t)blockIdx.x * blockDim.x + threadIdx.x;
    reinterpret_cast<float4*>(g_agg)[i] = make_float4(0.f, 0.f, 0.f, 0.f);
}
// round weights to tf32 (RN) once, keep [K][N] layout so cp.async can stream them
__global__ void prep_kernel(const float* __restrict__ eW1, const float* __restrict__ eW2,
                            const float* __restrict__ nW1, const float* __restrict__ nW2) {
    int i = blockIdx.x * blockDim.x + threadIdx.x;
    if (i < 98304)       g_W1e[i]          = totf(eW1[i]);
    else if (i < 131072) g_W2e[i - 98304]  = totf(eW2[i - 98304]);
    else if (i < 196608) g_W1n[i - 131072] = totf(nW1[i - 131072]);
    else if (i < 229376) g_W2n[i - 196608] = totf(nW2[i - 196608]);
}

// ------------------------------ edge kernel ---------------------------------
// tile = 128 edges, 512 threads (16 warps, 4M x 4N).
// GEMM1 [128,384]x[384,256] -> H(silu) -> GEMM2 [128,256]x[256,128] -> LN -> scatter
__global__ void __launch_bounds__(512, 1)
edge_kernel(const float* __restrict__ efeat, const float* __restrict__ gridf,
            const float* __restrict__ mesh, const int* __restrict__ src,
            const int* __restrict__ dst,
            const float* __restrict__ b1, const float* __restrict__ b2,
            const float* __restrict__ gam, const float* __restrict__ bet)
{
    extern __shared__ float sm[];
    const uint32_t sb4 = smem_u32(sm);
    const int tid  = threadIdx.x;
    const int warp = tid >> 5, lane = tid & 31;
    const int wm = warp >> 2, wn = warp & 3;
    const int e0 = blockIdx.x * 128;

    if (tid < 64) ((float4*)(sm + S_B1f))[tid] = ((const float4*)b1)[tid];
    else if (tid < 96)  ((float4*)(sm + S_B2f))[tid - 64] = ((const float4*)b2)[tid - 64];
    else if (tid < 128) ((float4*)(sm + S_Gf ))[tid - 96] = ((const float4*)gam)[tid - 96];
    else if (tid < 160) ((float4*)(sm + S_BTf))[tid - 128] = ((const float4*)bet)[tid - 128];

    // gather row assignment: 4 threads per row
    const int r  = tid >> 2;
    const int cb = (tid & 3) * 8;
    const int sidx = __ldg(&src[e0 + r]);
    const int didx = __ldg(&dst[e0 + r]);
    const float* rowE = efeat + (size_t)(e0 + r) * 128;
    const float* rowM = mesh  + (size_t)sidx * 128;
    const float* rowG = gridf + (size_t)didx * 128;

    auto stageA = [&](int c) {
        float* ab = sm + S_A0f + (c & 1) * 4608;
        const float* rp = (c < 4) ? rowE : (c < 8) ? rowM : rowG;
        const float4* gp = (const float4*)(rp + (c & 3) * 32 + cb);
        float4 v0 = __ldg(gp), v1 = __ldg(gp + 1);
        float* d = ab + r * LDA + cb;
        d[0] = totf(v0.x); d[1] = totf(v0.y); d[2] = totf(v0.z); d[3] = totf(v0.w);
        d[4] = totf(v1.x); d[5] = totf(v1.y); d[6] = totf(v1.z); d[7] = totf(v1.w);
    };
    auto stageB1 = [&](int c) {
        uint32_t bb = sb4 + (uint32_t)(S_B0f + (c & 1) * 8320) * 4;
        const float* gw = g_W1e + c * 32 * 256;
        #pragma unroll
        for (int i = 0; i < 4; ++i) {
            int id = tid + 512 * i; int rw = id >> 6, c16 = id & 63;
            cpa16(bb + (uint32_t)(rw * LDB1 + c16 * 4) * 4, gw + rw * 256 + c16 * 4);
        }
    };
    auto stageB2 = [&](int c) {
        uint32_t bb = sb4 + (uint32_t)(S_B20f + (c & 1) * 4224) * 4;
        const float* gw = g_W2e + c * 32 * 128;
        #pragma unroll
        for (int i = 0; i < 2; ++i) {
            int id = tid + 512 * i; int rw = id >> 5, c16 = id & 31;
            cpa16(bb + (uint32_t)(rw * LDB2 + c16 * 4) * 4, gw + rw * 128 + c16 * 4);
        }
    };

    // ---------------- GEMM1 ----------------
    wmma::fragment<wmma::accumulator, 16, 16, 8, float> acc[2][4];
    #pragma unroll
    for (int i = 0; i < 2; i++)
        #pragma unroll
        for (int j = 0; j < 4; j++) wmma::fill_fragment(acc[i][j], 0.f);

    stageA(0); stageB1(0);
    cp_commit(); cp_wait0(); __syncthreads();

    #pragma unroll 1
    for (int c = 0; c < 12; ++c) {
        if (c + 1 < 12) { stageA(c + 1); stageB1(c + 1); }
        cp_commit();
        const float* ab = sm + S_A0f + (c & 1) * 4608;
        const float* bb = sm + S_B0f + (c & 1) * 8320;
        #pragma unroll
        for (int kk = 0; kk < 32; kk += 8) {
            wmma::fragment<wmma::matrix_a, 16, 16, 8, wmma::precision::tf32, wmma::row_major> a0, a1;
            wmma::load_matrix_sync(a0, ab + (wm * 32)      * LDA + kk, LDA);
            wmma::load_matrix_sync(a1, ab + (wm * 32 + 16) * LDA + kk, LDA);
            #pragma unroll
            for (int j = 0; j < 4; j++) {
                wmma::fragment<wmma::matrix_b, 16, 16, 8, wmma::precision::tf32, wmma::row_major> b;
                wmma::load_matrix_sync(b, bb + kk * LDB1 + wn * 64 + j * 16, LDB1);
                wmma::mma_sync(acc[0][j], a0, b, acc[0][j]);
                wmma::mma_sync(acc[1][j], a1, b, acc[1][j]);
            }
        }
        cp_wait0();
        __syncthreads();
    }

    // store H, bias + SiLU (tf32-rounded in place)
    #pragma unroll
    for (int i = 0; i < 2; i++)
        #pragma unroll
        for (int j = 0; j < 4; j++)
            wmma::store_matrix_sync(sm + S_Hf + (wm * 32 + i * 16) * LDH + wn * 64 + j * 16,
                                    acc[i][j], LDH, wmma::mem_row_major);
    __syncthreads();
    #pragma unroll
    for (int i = 0; i < 16; i++) {
        int f = tid + 512 * i; int rr = f >> 6, c4 = f & 63;
        float* p = sm + S_Hf + rr * LDH + c4 * 4;
        float4 v = *reinterpret_cast<float4*>(p);
        float4 bb = *reinterpret_cast<const float4*>(sm + S_B1f + c4 * 4);
        float h0 = v.x + bb.x, h1 = v.y + bb.y, h2 = v.z + bb.z, h3 = v.w + bb.w;
        p[0] = totf(h0 / (1.f + __expf(-h0)));
        p[1] = totf(h1 / (1.f + __expf(-h1)));
        p[2] = totf(h2 / (1.f + __expf(-h2)));
        p[3] = totf(h3 / (1.f + __expf(-h3)));
    }
    stageB2(0);
    cp_commit(); cp_wait0(); __syncthreads();

    // ---------------- GEMM2 ----------------
    wmma::fragment<wmma::accumulator, 16, 16, 8, float> acc2[2][2];
    #pragma unroll
    for (int i = 0; i < 2; i++)
        #pragma unroll
        for (int j = 0; j < 2; j++) wmma::fill_fragment(acc2[i][j], 0.f);

    #pragma unroll 1
    for (int c = 0; c < 8; ++c) {
        if (c + 1 < 8) stageB2(c + 1);
        cp_commit();
        const float* bb = sm + S_B20f + (c & 1) * 4224;
        #pragma unroll
        for (int kk = 0; kk < 32; kk += 8) {
            wmma::fragment<wmma::matrix_a, 16, 16, 8, wmma::precision::tf32, wmma::row_major> a0, a1;
            wmma::load_matrix_sync(a0, sm + S_Hf + (wm * 32)      * LDH + c * 32 + kk, LDH);
            wmma::load_matrix_sync(a1, sm + S_Hf + (wm * 32 + 16) * LDH + c * 32 + kk, LDH);
            #pragma unroll
            for (int j = 0; j < 2; j++) {
                wmma::fragment<wmma::matrix_b, 16, 16, 8, wmma::precision::tf32, wmma::row_major> b;
                wmma::load_matrix_sync(b, bb + kk * LDB2 + wn * 32 + j * 16, LDB2);
                wmma::mma_sync(acc2[0][j], a0, b, acc2[0][j]);
                wmma::mma_sync(acc2[1][j], a1, b, acc2[1][j]);
            }
        }
        cp_wait0();
        __syncthreads();
    }
    #pragma unroll
    for (int i = 0; i < 2; i++)
        #pragma unroll
        for (int j = 0; j < 2; j++)
            wmma::store_matrix_sync(sm + S_Yf + (wm * 32 + i * 16) * LDY + wn * 32 + j * 16,
                                    acc2[i][j], LDY, wmma::mem_row_major);
    __syncthreads();

    // ---------------- +b2, LN, scatter ----------------
    #pragma unroll 1
    for (int i = 0; i < 8; i++) {
        int row = warp * 8 + i;
        float v[4], sum = 0.f, sq = 0.f;
        #pragma unroll
        for (int j = 0; j < 4; j++) {
            int c = lane + 32 * j;
            v[j] = sm[S_Yf + row * LDY + c] + sm[S_B2f + c];
            sum += v[j]; sq += v[j] * v[j];
        }
        #pragma unroll
        for (int o = 16; o > 0; o >>= 1) {
            sum += __shfl_xor_sync(0xFFFFFFFFu, sum, o);
            sq  += __shfl_xor_sync(0xFFFFFFFFu, sq,  o);
        }
        float mean = sum * (1.f / 128.f);
        float rstd = rsqrtf(sq * (1.f / 128.f) - mean * mean + 1e-5f);
        int dn = __ldg(&dst[e0 + row]);
        float* ap = g_agg + (size_t)dn * 128;
        #pragma unroll
        for (int j = 0; j < 4; j++) {
            int c = lane + 32 * j;
            float o = (v[j] - mean) * rstd * sm[S_Gf + c] + sm[S_BTf + c];
            atomicAdd(ap + c, o);
        }
    }
}

// ------------------------------ node kernel ---------------------------------
__global__ void __launch_bounds__(512, 1)
node_kernel(const float* __restrict__ gridf,
            const float* __restrict__ b1, const float* __restrict__ b2,
            const float* __restrict__ gam, const float* __restrict__ bet,
            float* __restrict__ out)
{
    extern __shared__ float sm[];
    const uint32_t sb4 = smem_u32(sm);
    const int tid  = threadIdx.x;
    const int warp = tid >> 5, lane = tid & 31;
    const int wm = warp >> 2, wn = warp & 3;
    const int n0 = blockIdx.x * 128;

    if (tid < 64) ((float4*)(sm + S_B1f))[tid] = ((const float4*)b1)[tid];
    else if (tid < 96)  ((float4*)(sm + S_B2f))[tid - 64] = ((const float4*)b2)[tid - 64];
    else if (tid < 128) ((float4*)(sm + S_Gf ))[tid - 96] = ((const float4*)gam)[tid - 96];
    else if (tid < 160) ((float4*)(sm + S_BTf))[tid - 128] = ((const float4*)bet)[tid - 128];

    const int r  = tid >> 2;
    const int cb = (tid & 3) * 8;
    const float* rowA = g_agg + (size_t)(n0 + r) * 128;
    const float* rowG = gridf + (size_t)(n0 + r) * 128;

    auto stageA = [&](int c) {
        float* ab = sm + S_A0f + (c & 1) * 4608;
        const float* rp = (c < 4) ? rowA : rowG;
        const float4* gp = (const float4*)(rp + (c & 3) * 32 + cb);
        float4 v0 = __ldg(gp), v1 = __ldg(gp + 1);
        float* d = ab + r * LDA + cb;
        d[0] = totf(v0.x); d[1] = totf(v0.y); d[2] = totf(v0.z); d[3] = totf(v0.w);
        d[4] = totf(v1.x); d[5] = totf(v1.y); d[6] = totf(v1.z); d[7] = totf(v1.w);
    };
    auto stageB1 = [&](int c) {
        uint32_t bb = sb4 + (uint32_t)(S_B0f + (c & 1) * 8320) * 4;
        const float* gw = g_W1n + c * 32 * 256;
        #pragma unroll
        for (int i = 0; i < 4; ++i) {
            int id = tid + 512 * i; int rw = id >> 6, c16 = id & 63;
            cpa16(bb + (uint32_t)(rw * LDB1 + c16 * 4) * 4, gw + rw * 256 + c16 * 4);
        }
    };
    auto stageB2 = [&](int c) {
        uint32_t bb = sb4 + (uint32_t)(S_B20f + (c & 1) * 4224) * 4;
        const float* gw = g_W2n + c * 32 * 128;
        #pragma unroll
        for (int i = 0; i < 2; ++i) {
            int id = tid + 512 * i; int rw = id >> 5, c16 = id & 31;
            cpa16(bb + (uint32_t)(rw * LDB2 + c16 * 4) * 4, gw + rw * 128 + c16 * 4);
        }
    };

    // ---------------- GEMM1 ----------------
    wmma::fragment<wmma::accumulator, 16, 16, 8, float> acc[2][4];
    #pragma unroll
    for (int i = 0; i < 2; i++)
        #pragma unroll
        for (int j = 0; j < 4; j++) wmma::fill_fragment(acc[i][j], 0.f);

    stageA(0); stageB1(0);
    cp_commit(); cp_wait0(); __syncthreads();

    #pragma unroll 1
    for (int c = 0; c < 8; ++c) {
        if (c + 1 < 8) { stageA(c + 1); stageB1(c + 1); }
        cp_commit();
        const float* ab = sm + S_A0f + (c & 1) * 4608;
        const float* bb = sm + S_B0f + (c & 1) * 8320;
        #pragma unroll
        for (int kk = 0; kk < 32; kk += 8) {
            wmma::fragment<wmma::matrix_a, 16, 16, 8, wmma::precision::tf32, wmma::row_major> a0, a1;
            wmma::load_matrix_sync(a0, ab + (wm * 32)      * LDA + kk, LDA);
            wmma::load_matrix_sync(a1, ab + (wm * 32 + 16) * LDA + kk, LDA);
            #pragma unroll
            for (int j = 0; j < 4; j++) {
                wmma::fragment<wmma::matrix_b, 16, 16, 8, wmma::precision::tf32, wmma::row_major> b;
                wmma::load_matrix_sync(b, bb + kk * LDB1 + wn * 64 + j * 16, LDB1);
                wmma::mma_sync(acc[0][j], a0, b, acc[0][j]);
                wmma::mma_sync(acc[1][j], a1, b, acc[1][j]);
            }
        }
        cp_wait0();
        __syncthreads();
    }

    #pragma unroll
    for (int i = 0; i < 2; i++)
        #pragma unroll
        for (int j = 0; j < 4; j++)
            wmma::store_matrix_sync(sm + S_Hf + (wm * 32 + i * 16) * LDH + wn * 64 + j * 16,
                                    acc[i][j], LDH, wmma::mem_row_major);
    __syncthreads();
    #pragma unroll
    for (int i = 0; i < 16; i++) {
        int f = tid + 512 * i; int rr = f >> 6, c4 = f & 63;
        float* p = sm + S_Hf + rr * LDH + c4 * 4;
        float4 v = *reinterpret_cast<float4*>(p);
        float4 bb = *reinterpret_cast<const float4*>(sm + S_B1f + c4 * 4);
        float h0 = v.x + bb.x, h1 = v.y + bb.y, h2 = v.z + bb.z, h3 = v.w + bb.w;
        p[0] = totf(h0 / (1.f + __expf(-h0)));
        p[1] = totf(h1 / (1.f + __expf(-h1)));
        p[2] = totf(h2 / (1.f + __expf(-h2)));
        p[3] = totf(h3 / (1.f + __expf(-h3)));
    }
    stageB2(0);
    cp_commit(); cp_wait0(); __syncthreads();

    // ---------------- GEMM2 ----------------
    wmma::fragment<wmma::accumulator, 16, 16, 8, float> acc2[2][2];
    #pragma unroll
    for (int i = 0; i < 2; i++)
        #pragma unroll
        for (int j = 0; j < 2; j++) wmma::fill_fragment(acc2[i][j], 0.f);

    #pragma unroll 1
    for (int c = 0; c < 8; ++c) {
        if (c + 1 < 8) stageB2(c + 1);
        cp_commit();
        const float* bb = sm + S_B20f + (c & 1) * 4224;
        #pragma unroll
        for (int kk = 0; kk < 32; kk += 8) {
            wmma::fragment<wmma::matrix_a, 16, 16, 8, wmma::precision::tf32, wmma::row_major> a0, a1;
            wmma::load_matrix_sync(a0, sm + S_Hf + (wm * 32)      * LDH + c * 32 + kk, LDH);
            wmma::load_matrix_sync(a1, sm + S_Hf + (wm * 32 + 16) * LDH + c * 32 + kk, LDH);
            #pragma unroll
            for (int j = 0; j < 2; j++) {
                wmma::fragment<wmma::matrix_b, 16, 16, 8, wmma::precision::tf32, wmma::row_major> b;
                wmma::load_matrix_sync(b, bb + kk * LDB2 + wn * 32 + j * 16, LDB2);
                wmma::mma_sync(acc2[0][j], a0, b, acc2[0][j]);
                wmma::mma_sync(acc2[1][j], a1, b, acc2[1][j]);
            }
        }
        cp_wait0();
        __syncthreads();
    }
    #pragma unroll
    for (int i = 0; i < 2; i++)
        #pragma unroll
        for (int j = 0; j < 2; j++)
            wmma::store_matrix_sync(sm + S_Yf + (wm * 32 + i * 16) * LDY + wn * 32 + j * 16,
                                    acc2[i][j], LDY, wmma::mem_row_major);
    __syncthreads();

    // ---------------- +b2, LN, affine, +residual ----------------
    #pragma unroll 1
    for (int i = 0; i < 8; i++) {
        int row = warp * 8 + i;
        float v[4], sum = 0.f, sq = 0.f;
        #pragma unroll
        for (int j = 0; j < 4; j++) {
            int c = lane + 32 * j;
            v[j] = sm[S_Yf + row * LDY + c] + sm[S_B2f + c];
            sum += v[j]; sq += v[j] * v[j];
        }
        #pragma unroll
        for (int o = 16; o > 0; o >>= 1) {
            sum += __shfl_xor_sync(0xFFFFFFFFu, sum, o);
            sq  += __shfl_xor_sync(0xFFFFFFFFu, sq,  o);
        }
        float mean = sum * (1.f / 128.f);
        float rstd = rsqrtf(sq * (1.f / 128.f) - mean * mean + 1e-5f);
        size_t base = (size_t)(n0 + row) * 128;
        #pragma unroll
        for (int j = 0; j < 4; j++) {
            int c = lane + 32 * j;
            float o = (v[j] - mean) * rstd * sm[S_Gf + c] + sm[S_BTf + c];
            out[base + c] = o + __ldg(&gridf[base + c]);
        }
    }
}

// ------------------------------ launch --------------------------------------
extern "C" void kernel_launch(void* const* d_in, const int* in_sizes, int n_in,
                              void* d_out, int out_size)
{
    const float* efeat = (const float*)d_in[0];
    const float* gridf = (const float*)d_in[1];
    const float* mesh  = (const float*)d_in[2];
    const int*   src   = (const int*)d_in[3];
    const int*   dst   = (const int*)d_in[4];
    const float* eW1   = (const float*)d_in[5];
    const float* eb1   = (const float*)d_in[6];
    const float* eW2   = (const float*)d_in[7];
    const float* eb2   = (const float*)d_in[8];
    const float* eg    = (const float*)d_in[9];
    const float* ebeta = (const float*)d_in[10];
    const float* nW1   = (const float*)d_in[11];
    const float* nb1   = (const float*)d_in[12];
    const float* nW2   = (const float*)d_in[13];
    const float* nb2   = (const float*)d_in[14];
    const float* ng    = (const float*)d_in[15];
    const float* nbeta = (const float*)d_in[16];
    float* out = (float*)d_out;

    const size_t smem = SMEM_FLOATS * sizeof(float);  // 171,008 B
    cudaFuncSetAttribute(edge_kernel, cudaFuncAttributeMaxDynamicSharedMemorySize, (int)smem);
    cudaFuncSetAttribute(node_kernel, cudaFuncAttributeMaxDynamicSharedMemorySize, (int)smem);

    zero_agg_kernel<<<8192, 1024>>>();
    prep_kernel<<<896, 256>>>(eW1, eW2, nW1, nW2);
    edge_kernel<<<N_EDGE / 128, 512, smem>>>(efeat, gridf, mesh, src, dst,
                                             eb1, eb2, eg, ebeta);
    node_kernel<<<N_GRID / 128, 512, smem>>>(gridf, nb1, nb2, ng, nbeta, out);
}

// round 4
// speedup vs baseline: 1.1974x; 1.1197x over previous
#include <cuda_runtime.h>
#include <mma.h>
#include <cstdint>

using namespace nvcuda;

#define N_MESH 40962
#define N_GRID 262144
#define N_EDGE 786432

// ------------------------------ device scratch ------------------------------
__device__ float g_agg[(size_t)N_GRID * 128];
__device__ float g_W1e[384 * 256];   // eW1 [K][N], tf32-RN pre-rounded
__device__ float g_W2e[256 * 128];
__device__ float g_W1n[256 * 256];
__device__ float g_W2n[256 * 128];

// ------------------------------ tiling --------------------------------------
// 64 rows per CTA, 256 threads (8 warps: 2M x 4N), 2 CTAs/SM.
#define MT    64
#define NTHR  256

// ------------------------------ smem layout (float offsets) -----------------
#define S_B1f  0            // 256
#define S_B2f  256          // 128
#define S_Gf   384          // 128
#define S_BTf  512          // 128
#define S_A0f  640          // 2 x (64 x 36)  = 4608         -> ends 5248
#define S_B0f  5248         // 2 x (32 x 260) = 16640        -> ends 21888
#define S_Hf   640          // 64 x 260 = 16640 (overlaps dead A/B0) -> ends 17280
#define S_B20f 17280        // 2 x (32 x 132) = 8448         -> ends 25728
#define S_Yf   640          // 64 x 132 = 8448 (overlaps dead H)
#define SMEM_FLOATS 25728   // 102,912 bytes -> 2 CTAs/SM (205,824 < 227KB)

#define LDA  36
#define LDB1 260
#define LDH  260
#define LDB2 132
#define LDY  132

// ------------------------------ helpers -------------------------------------
static __device__ __forceinline__ float totf(float x) { return wmma::__float_to_tf32(x); }

__device__ __forceinline__ uint32_t smem_u32(const void* p) {
    uint32_t a;
    asm("{ .reg .u64 t; cvta.to.shared.u64 t, %1; cvt.u32.u64 %0, t; }" : "=r"(a) : "l"(p));
    return a;
}
__device__ __forceinline__ void cpa16(uint32_t s, const void* g) {
    asm volatile("cp.async.cg.shared.global [%0], [%1], 16;" :: "r"(s), "l"(g) : "memory");
}
__device__ __forceinline__ void cp_commit() {
    asm volatile("cp.async.commit_group;" ::: "memory");
}
__device__ __forceinline__ void cp_wait0() {
    asm volatile("cp.async.wait_group 0;" ::: "memory");
}
__device__ __forceinline__ void red_add_v4(float* p, float4 v) {
    asm volatile("red.global.add.v4.f32 [%0], {%1, %2, %3, %4};"
                 :: "l"(p), "f"(v.x), "f"(v.y), "f"(v.z), "f"(v.w) : "memory");
}

// ------------------------------ prep kernels --------------------------------
__global__ void zero_agg_kernel() {
    size_t i = (size_t)blockIdx.x * blockDim.x + threadIdx.x;
    reinterpret_cast<float4*>(g_agg)[i] = make_float4(0.f, 0.f, 0.f, 0.f);
}
__global__ void prep_kernel(const float* __restrict__ eW1, const float* __restrict__ eW2,
                            const float* __restrict__ nW1, const float* __restrict__ nW2) {
    int i = blockIdx.x * blockDim.x + threadIdx.x;
    if (i < 98304)       g_W1e[i]          = totf(eW1[i]);
    else if (i < 131072) g_W2e[i - 98304]  = totf(eW2[i - 98304]);
    else if (i < 196608) g_W1n[i - 131072] = totf(nW1[i - 131072]);
    else if (i < 229376) g_W2n[i - 196608] = totf(nW2[i - 196608]);
}

// ------------------------------ edge kernel ---------------------------------
// tile = 64 edges. GEMM1 [64,384]x[384,256] -> H(silu) -> GEMM2 [64,256]x[256,128]
// -> +b2 -> LN -> red.v4 scatter to g_agg[dst]
__global__ void __launch_bounds__(NTHR, 2)
edge_kernel(const float* __restrict__ efeat, const float* __restrict__ gridf,
            const float* __restrict__ mesh, const int* __restrict__ src,
            const int* __restrict__ dst,
            const float* __restrict__ b1, const float* __restrict__ b2,
            const float* __restrict__ gam, const float* __restrict__ bet)
{
    extern __shared__ float sm[];
    const uint32_t sb4 = smem_u32(sm);
    const int tid  = threadIdx.x;
    const int warp = tid >> 5, lane = tid & 31;
    const int wm = warp >> 2, wn = warp & 3;
    const int e0 = blockIdx.x * MT;

    if (tid < 64) ((float4*)(sm + S_B1f))[tid] = ((const float4*)b1)[tid];
    else if (tid < 96)  ((float4*)(sm + S_B2f))[tid - 64] = ((const float4*)b2)[tid - 64];
    else if (tid < 128) ((float4*)(sm + S_Gf ))[tid - 96] = ((const float4*)gam)[tid - 96];
    else if (tid < 160) ((float4*)(sm + S_BTf))[tid - 128] = ((const float4*)bet)[tid - 128];

    // gather: 4 threads per row
    const int r  = tid >> 2;
    const int cb = (tid & 3) * 8;
    const int sidx = __ldg(&src[e0 + r]);
    const int didx = __ldg(&dst[e0 + r]);
    const float* rowE = efeat + (size_t)(e0 + r) * 128;
    const float* rowM = mesh  + (size_t)sidx * 128;
    const float* rowG = gridf + (size_t)didx * 128;

    auto stageA = [&](int c) {
        float* ab = sm + S_A0f + (c & 1) * (MT * LDA);
        const float* rp = (c < 4) ? rowE : (c < 8) ? rowM : rowG;
        const float4* gp = (const float4*)(rp + (c & 3) * 32 + cb);
        float4 v0 = __ldg(gp), v1 = __ldg(gp + 1);
        float* d = ab + r * LDA + cb;
        d[0] = totf(v0.x); d[1] = totf(v0.y); d[2] = totf(v0.z); d[3] = totf(v0.w);
        d[4] = totf(v1.x); d[5] = totf(v1.y); d[6] = totf(v1.z); d[7] = totf(v1.w);
    };
    auto stageB1 = [&](int c) {
        uint32_t bb = sb4 + (uint32_t)(S_B0f + (c & 1) * (32 * LDB1)) * 4;
        const float* gw = g_W1e + c * 32 * 256;
        #pragma unroll
        for (int i = 0; i < 8; ++i) {
            int id = tid + NTHR * i; int rw = id >> 6, c16 = id & 63;
            cpa16(bb + (uint32_t)(rw * LDB1 + c16 * 4) * 4, gw + rw * 256 + c16 * 4);
        }
    };
    auto stageB2 = [&](int c) {
        uint32_t bb = sb4 + (uint32_t)(S_B20f + (c & 1) * (32 * LDB2)) * 4;
        const float* gw = g_W2e + c * 32 * 128;
        #pragma unroll
        for (int i = 0; i < 4; ++i) {
            int id = tid + NTHR * i; int rw = id >> 5, c16 = id & 31;
            cpa16(bb + (uint32_t)(rw * LDB2 + c16 * 4) * 4, gw + rw * 128 + c16 * 4);
        }
    };

    // ---------------- GEMM1 ----------------
    wmma::fragment<wmma::accumulator, 16, 16, 8, float> acc[2][4];
    #pragma unroll
    for (int i = 0; i < 2; i++)
        #pragma unroll
        for (int j = 0; j < 4; j++) wmma::fill_fragment(acc[i][j], 0.f);

    stageA(0); stageB1(0);
    cp_commit(); cp_wait0(); __syncthreads();

    #pragma unroll 1
    for (int c = 0; c < 12; ++c) {
        if (c + 1 < 12) { stageA(c + 1); stageB1(c + 1); }
        cp_commit();
        const float* ab = sm + S_A0f + (c & 1) * (MT * LDA);
        const float* bb = sm + S_B0f + (c & 1) * (32 * LDB1);
        #pragma unroll
        for (int kk = 0; kk < 32; kk += 8) {
            wmma::fragment<wmma::matrix_a, 16, 16, 8, wmma::precision::tf32, wmma::row_major> a0, a1;
            wmma::load_matrix_sync(a0, ab + (wm * 32)      * LDA + kk, LDA);
            wmma::load_matrix_sync(a1, ab + (wm * 32 + 16) * LDA + kk, LDA);
            #pragma unroll
            for (int j = 0; j < 4; j++) {
                wmma::fragment<wmma::matrix_b, 16, 16, 8, wmma::precision::tf32, wmma::row_major> b;
                wmma::load_matrix_sync(b, bb + kk * LDB1 + wn * 64 + j * 16, LDB1);
                wmma::mma_sync(acc[0][j], a0, b, acc[0][j]);
                wmma::mma_sync(acc[1][j], a1, b, acc[1][j]);
            }
        }
        cp_wait0();
        __syncthreads();
    }

    // store H, bias + SiLU (tf32-rounded in place)
    #pragma unroll
    for (int i = 0; i < 2; i++)
        #pragma unroll
        for (int j = 0; j < 4; j++)
            wmma::store_matrix_sync(sm + S_Hf + (wm * 32 + i * 16) * LDH + wn * 64 + j * 16,
                                    acc[i][j], LDH, wmma::mem_row_major);
    __syncthreads();
    #pragma unroll
    for (int i = 0; i < 16; i++) {
        int f = tid + NTHR * i; int rr = f >> 6, c4 = f & 63;
        float* p = sm + S_Hf + rr * LDH + c4 * 4;
        float4 v = *reinterpret_cast<float4*>(p);
        float4 bb = *reinterpret_cast<const float4*>(sm + S_B1f + c4 * 4);
        float h0 = v.x + bb.x, h1 = v.y + bb.y, h2 = v.z + bb.z, h3 = v.w + bb.w;
        p[0] = totf(h0 / (1.f + __expf(-h0)));
        p[1] = totf(h1 / (1.f + __expf(-h1)));
        p[2] = totf(h2 / (1.f + __expf(-h2)));
        p[3] = totf(h3 / (1.f + __expf(-h3)));
    }
    stageB2(0);
    cp_commit(); cp_wait0(); __syncthreads();

    // ---------------- GEMM2 ----------------
    wmma::fragment<wmma::accumulator, 16, 16, 8, float> acc2[2][2];
    #pragma unroll
    for (int i = 0; i < 2; i++)
        #pragma unroll
        for (int j = 0; j < 2; j++) wmma::fill_fragment(acc2[i][j], 0.f);

    #pragma unroll 1
    for (int c = 0; c < 8; ++c) {
        if (c + 1 < 8) stageB2(c + 1);
        cp_commit();
        const float* bb = sm + S_B20f + (c & 1) * (32 * LDB2);
        #pragma unroll
        for (int kk = 0; kk < 32; kk += 8) {
            wmma::fragment<wmma::matrix_a, 16, 16, 8, wmma::precision::tf32, wmma::row_major> a0, a1;
            wmma::load_matrix_sync(a0, sm + S_Hf + (wm * 32)      * LDH + c * 32 + kk, LDH);
            wmma::load_matrix_sync(a1, sm + S_Hf + (wm * 32 + 16) * LDH + c * 32 + kk, LDH);
            #pragma unroll
            for (int j = 0; j < 2; j++) {
                wmma::fragment<wmma::matrix_b, 16, 16, 8, wmma::precision::tf32, wmma::row_major> b;
                wmma::load_matrix_sync(b, bb + kk * LDB2 + wn * 32 + j * 16, LDB2);
                wmma::mma_sync(acc2[0][j], a0, b, acc2[0][j]);
                wmma::mma_sync(acc2[1][j], a1, b, acc2[1][j]);
            }
        }
        cp_wait0();
        __syncthreads();
    }
    #pragma unroll
    for (int i = 0; i < 2; i++)
        #pragma unroll
        for (int j = 0; j < 2; j++)
            wmma::store_matrix_sync(sm + S_Yf + (wm * 32 + i * 16) * LDY + wn * 32 + j * 16,
                                    acc2[i][j], LDY, wmma::mem_row_major);
    __syncthreads();

    // ---------------- +b2, LN, vector-red scatter ----------------
    float4 bb2 = *reinterpret_cast<const float4*>(sm + S_B2f + lane * 4);
    float4 gg  = *reinterpret_cast<const float4*>(sm + S_Gf  + lane * 4);
    float4 bt  = *reinterpret_cast<const float4*>(sm + S_BTf + lane * 4);
    #pragma unroll 1
    for (int i = 0; i < 8; i++) {
        int row = warp * 8 + i;
        float4 v = *reinterpret_cast<const float4*>(sm + S_Yf + row * LDY + lane * 4);
        v.x += bb2.x; v.y += bb2.y; v.z += bb2.z; v.w += bb2.w;
        float sum = v.x + v.y + v.z + v.w;
        float sq  = v.x * v.x + v.y * v.y + v.z * v.z + v.w * v.w;
        #pragma unroll
        for (int o = 16; o > 0; o >>= 1) {
            sum += __shfl_xor_sync(0xFFFFFFFFu, sum, o);
            sq  += __shfl_xor_sync(0xFFFFFFFFu, sq,  o);
        }
        float mean = sum * (1.f / 128.f);
        float rstd = rsqrtf(sq * (1.f / 128.f) - mean * mean + 1e-5f);
        int dn = __ldg(&dst[e0 + row]);
        float4 o;
        o.x = (v.x - mean) * rstd * gg.x + bt.x;
        o.y = (v.y - mean) * rstd * gg.y + bt.y;
        o.z = (v.z - mean) * rstd * gg.z + bt.z;
        o.w = (v.w - mean) * rstd * gg.w + bt.w;
        red_add_v4(g_agg + (size_t)dn * 128 + lane * 4, o);
    }
}

// ------------------------------ node kernel ---------------------------------
__global__ void __launch_bounds__(NTHR, 2)
node_kernel(const float* __restrict__ gridf,
            const float* __restrict__ b1, const float* __restrict__ b2,
            const float* __restrict__ gam, const float* __restrict__ bet,
            float* __restrict__ out)
{
    extern __shared__ float sm[];
    const uint32_t sb4 = smem_u32(sm);
    const int tid  = threadIdx.x;
    const int warp = tid >> 5, lane = tid & 31;
    const int wm = warp >> 2, wn = warp & 3;
    const int n0 = blockIdx.x * MT;

    if (tid < 64) ((float4*)(sm + S_B1f))[tid] = ((const float4*)b1)[tid];
    else if (tid < 96)  ((float4*)(sm + S_B2f))[tid - 64] = ((const float4*)b2)[tid - 64];
    else if (tid < 128) ((float4*)(sm + S_Gf ))[tid - 96] = ((const float4*)gam)[tid - 96];
    else if (tid < 160) ((float4*)(sm + S_BTf))[tid - 128] = ((const float4*)bet)[tid - 128];

    const int r  = tid >> 2;
    const int cb = (tid & 3) * 8;
    const float* rowA = g_agg + (size_t)(n0 + r) * 128;
    const float* rowG = gridf + (size_t)(n0 + r) * 128;

    auto stageA = [&](int c) {
        float* ab = sm + S_A0f + (c & 1) * (MT * LDA);
        const float* rp = (c < 4) ? rowA : rowG;
        const float4* gp = (const float4*)(rp + (c & 3) * 32 + cb);
        float4 v0 = __ldg(gp), v1 = __ldg(gp + 1);
        float* d = ab + r * LDA + cb;
        d[0] = totf(v0.x); d[1] = totf(v0.y); d[2] = totf(v0.z); d[3] = totf(v0.w);
        d[4] = totf(v1.x); d[5] = totf(v1.y); d[6] = totf(v1.z); d[7] = totf(v1.w);
    };
    auto stageB1 = [&](int c) {
        uint32_t bb = sb4 + (uint32_t)(S_B0f + (c & 1) * (32 * LDB1)) * 4;
        const float* gw = g_W1n + c * 32 * 256;
        #pragma unroll
        for (int i = 0; i < 8; ++i) {
            int id = tid + NTHR * i; int rw = id >> 6, c16 = id & 63;
            cpa16(bb + (uint32_t)(rw * LDB1 + c16 * 4) * 4, gw + rw * 256 + c16 * 4);
        }
    };
    auto stageB2 = [&](int c) {
        uint32_t bb = sb4 + (uint32_t)(S_B20f + (c & 1) * (32 * LDB2)) * 4;
        const float* gw = g_W2n + c * 32 * 128;
        #pragma unroll
        for (int i = 0; i < 4; ++i) {
            int id = tid + NTHR * i; int rw = id >> 5, c16 = id & 31;
            cpa16(bb + (uint32_t)(rw * LDB2 + c16 * 4) * 4, gw + rw * 128 + c16 * 4);
        }
    };

    // ---------------- GEMM1 ----------------
    wmma::fragment<wmma::accumulator, 16, 16, 8, float> acc[2][4];
    #pragma unroll
    for (int i = 0; i < 2; i++)
        #pragma unroll
        for (int j = 0; j < 4; j++) wmma::fill_fragment(acc[i][j], 0.f);

    stageA(0); stageB1(0);
    cp_commit(); cp_wait0(); __syncthreads();

    #pragma unroll 1
    for (int c = 0; c < 8; ++c) {
        if (c + 1 < 8) { stageA(c + 1); stageB1(c + 1); }
        cp_commit();
        const float* ab = sm + S_A0f + (c & 1) * (MT * LDA);
        const float* bb = sm + S_B0f + (c & 1) * (32 * LDB1);
        #pragma unroll
        for (int kk = 0; kk < 32; kk += 8) {
            wmma::fragment<wmma::matrix_a, 16, 16, 8, wmma::precision::tf32, wmma::row_major> a0, a1;
            wmma::load_matrix_sync(a0, ab + (wm * 32)      * LDA + kk, LDA);
            wmma::load_matrix_sync(a1, ab + (wm * 32 + 16) * LDA + kk, LDA);
            #pragma unroll
            for (int j = 0; j < 4; j++) {
                wmma::fragment<wmma::matrix_b, 16, 16, 8, wmma::precision::tf32, wmma::row_major> b;
                wmma::load_matrix_sync(b, bb + kk * LDB1 + wn * 64 + j * 16, LDB1);
                wmma::mma_sync(acc[0][j], a0, b, acc[0][j]);
                wmma::mma_sync(acc[1][j], a1, b, acc[1][j]);
            }
        }
        cp_wait0();
        __syncthreads();
    }

    #pragma unroll
    for (int i = 0; i < 2; i++)
        #pragma unroll
        for (int j = 0; j < 4; j++)
            wmma::store_matrix_sync(sm + S_Hf + (wm * 32 + i * 16) * LDH + wn * 64 + j * 16,
                                    acc[i][j], LDH, wmma::mem_row_major);
    __syncthreads();
    #pragma unroll
    for (int i = 0; i < 16; i++) {
        int f = tid + NTHR * i; int rr = f >> 6, c4 = f & 63;
        float* p = sm + S_Hf + rr * LDH + c4 * 4;
        float4 v = *reinterpret_cast<float4*>(p);
        float4 bb = *reinterpret_cast<const float4*>(sm + S_B1f + c4 * 4);
        float h0 = v.x + bb.x, h1 = v.y + bb.y, h2 = v.z + bb.z, h3 = v.w + bb.w;
        p[0] = totf(h0 / (1.f + __expf(-h0)));
        p[1] = totf(h1 / (1.f + __expf(-h1)));
        p[2] = totf(h2 / (1.f + __expf(-h2)));
        p[3] = totf(h3 / (1.f + __expf(-h3)));
    }
    stageB2(0);
    cp_commit(); cp_wait0(); __syncthreads();

    // ---------------- GEMM2 ----------------
    wmma::fragment<wmma::accumulator, 16, 16, 8, float> acc2[2][2];
    #pragma unroll
    for (int i = 0; i < 2; i++)
        #pragma unroll
        for (int j = 0; j < 2; j++) wmma::fill_fragment(acc2[i][j], 0.f);

    #pragma unroll 1
    for (int c = 0; c < 8; ++c) {
        if (c + 1 < 8) stageB2(c + 1);
        cp_commit();
        const float* bb = sm + S_B20f + (c & 1) * (32 * LDB2);
        #pragma unroll
        for (int kk = 0; kk < 32; kk += 8) {
            wmma::fragment<wmma::matrix_a, 16, 16, 8, wmma::precision::tf32, wmma::row_major> a0, a1;
            wmma::load_matrix_sync(a0, sm + S_Hf + (wm * 32)      * LDH + c * 32 + kk, LDH);
            wmma::load_matrix_sync(a1, sm + S_Hf + (wm * 32 + 16) * LDH + c * 32 + kk, LDH);
            #pragma unroll
            for (int j = 0; j < 2; j++) {
                wmma::fragment<wmma::matrix_b, 16, 16, 8, wmma::precision::tf32, wmma::row_major> b;
                wmma::load_matrix_sync(b, bb + kk * LDB2 + wn * 32 + j * 16, LDB2);
                wmma::mma_sync(acc2[0][j], a0, b, acc2[0][j]);
                wmma::mma_sync(acc2[1][j], a1, b, acc2[1][j]);
            }
        }
        cp_wait0();
        __syncthreads();
    }
    #pragma unroll
    for (int i = 0; i < 2; i++)
        #pragma unroll
        for (int j = 0; j < 2; j++)
            wmma::store_matrix_sync(sm + S_Yf + (wm * 32 + i * 16) * LDY + wn * 32 + j * 16,
                                    acc2[i][j], LDY, wmma::mem_row_major);
    __syncthreads();

    // ---------------- +b2, LN, affine, +residual ----------------
    float4 bb2 = *reinterpret_cast<const float4*>(sm + S_B2f + lane * 4);
    float4 gg  = *reinterpret_cast<const float4*>(sm + S_Gf  + lane * 4);
    float4 bt  = *reinterpret_cast<const float4*>(sm + S_BTf + lane * 4);
    #pragma unroll 1
    for (int i = 0; i < 8; i++) {
        int row = warp * 8 + i;
        float4 v = *reinterpret_cast<const float4*>(sm + S_Yf + row * LDY + lane * 4);
        v.x += bb2.x; v.y += bb2.y; v.z += bb2.z; v.w += bb2.w;
        float sum = v.x + v.y + v.z + v.w;
        float sq  = v.x * v.x + v.y * v.y + v.z * v.z + v.w * v.w;
        #pragma unroll
        for (int o = 16; o > 0; o >>= 1) {
            sum += __shfl_xor_sync(0xFFFFFFFFu, sum, o);
            sq  += __shfl_xor_sync(0xFFFFFFFFu, sq,  o);
        }
        float mean = sum * (1.f / 128.f);
        float rstd = rsqrtf(sq * (1.f / 128.f) - mean * mean + 1e-5f);
        size_t base = (size_t)(n0 + row) * 128;
        float4 gv = __ldg((const float4*)(gridf + base) + lane);
        float4 o;
        o.x = (v.x - mean) * rstd * gg.x + bt.x + gv.x;
        o.y = (v.y - mean) * rstd * gg.y + bt.y + gv.y;
        o.z = (v.z - mean) * rstd * gg.z + bt.z + gv.z;
        o.w = (v.w - mean) * rstd * gg.w + bt.w + gv.w;
        *((float4*)(out + base) + lane) = o;
    }
}

// ------------------------------ launch --------------------------------------
extern "C" void kernel_launch(void* const* d_in, const int* in_sizes, int n_in,
                              void* d_out, int out_size)
{
    const float* efeat = (const float*)d_in[0];
    const float* gridf = (const float*)d_in[1];
    const float* mesh  = (const float*)d_in[2];
    const int*   src   = (const int*)d_in[3];
    const int*   dst   = (const int*)d_in[4];
    const float* eW1   = (const float*)d_in[5];
    const float* eb1   = (const float*)d_in[6];
    const float* eW2   = (const float*)d_in[7];
    const float* eb2   = (const float*)d_in[8];
    const float* eg    = (const float*)d_in[9];
    const float* ebeta = (const float*)d_in[10];
    const float* nW1   = (const float*)d_in[11];
    const float* nb1   = (const float*)d_in[12];
    const float* nW2   = (const float*)d_in[13];
    const float* nb2   = (const float*)d_in[14];
    const float* ng    = (const float*)d_in[15];
    const float* nbeta = (const float*)d_in[16];
    float* out = (float*)d_out;

    const size_t smem = SMEM_FLOATS * sizeof(float);  // 102,912 B
    cudaFuncSetAttribute(edge_kernel, cudaFuncAttributeMaxDynamicSharedMemorySize, (int)smem);
    cudaFuncSetAttribute(node_kernel, cudaFuncAttributeMaxDynamicSharedMemorySize, (int)smem);

    zero_agg_kernel<<<8192, 1024>>>();
    prep_kernel<<<896, 256>>>(eW1, eW2, nW1, nW2);
    edge_kernel<<<N_EDGE / MT, NTHR, smem>>>(efeat, gridf, mesh, src, dst,
                                             eb1, eb2, eg, ebeta);
    node_kernel<<<N_GRID / MT, NTHR, smem>>>(gridf, nb1, nb2, ng, nbeta, out);
}

// round 5
// speedup vs baseline: 1.2081x; 1.0090x over previous
#include <cuda_runtime.h>
#include <mma.h>
#include <cstdint>

using namespace nvcuda;

#define N_MESH 40962
#define N_GRID 262144
#define N_EDGE 786432

// ------------------------------ device scratch ------------------------------
__device__ float g_agg[(size_t)N_GRID * 128];
__device__ float g_W1e[384 * 256];   // eW1 [K][N], tf32-RN pre-rounded
__device__ float g_W2e[256 * 128];
__device__ float g_W1n[256 * 256];
__device__ float g_W2n[256 * 128];

// ------------------------------ tiling --------------------------------------
// 64 rows per CTA, 128 threads (4 warps, each 64x64 tile on GEMM1), 2 CTAs/SM.
#define MT    64
#define NTHR  128

// ------------------------------ smem layout (float offsets) -----------------
#define S_B1f  0            // 256
#define S_B2f  256          // 128
#define S_Gf   384          // 128
#define S_BTf  512          // 128
#define S_A0f  640          // 2 x (64 x 36)  = 4608         -> ends 5248
#define S_B0f  5248         // 2 x (32 x 260) = 16640        -> ends 21888
#define S_Hf   640          // 64 x 260 = 16640 (overlaps dead A/B0)
#define S_B20f 17280        // 2 x (32 x 132) = 8448         -> ends 25728
#define S_Yf   640          // 64 x 132 = 8448 (overlaps dead H)
#define SMEM_FLOATS 25728   // 102,912 bytes -> 2 CTAs/SM

#define LDA  36
#define LDB1 260
#define LDH  260
#define LDB2 132
#define LDY  132

// ------------------------------ helpers -------------------------------------
static __device__ __forceinline__ float totf(float x) { return wmma::__float_to_tf32(x); }

__device__ __forceinline__ uint32_t smem_u32(const void* p) {
    uint32_t a;
    asm("{ .reg .u64 t; cvta.to.shared.u64 t, %1; cvt.u32.u64 %0, t; }" : "=r"(a) : "l"(p));
    return a;
}
__device__ __forceinline__ void cpa16(uint32_t s, const void* g) {
    asm volatile("cp.async.cg.shared.global [%0], [%1], 16;" :: "r"(s), "l"(g) : "memory");
}
__device__ __forceinline__ void cp_commit() {
    asm volatile("cp.async.commit_group;" ::: "memory");
}
__device__ __forceinline__ void cp_wait0() {
    asm volatile("cp.async.wait_group 0;" ::: "memory");
}
__device__ __forceinline__ void red_add_v4(float* p, float4 v) {
    asm volatile("red.global.add.v4.f32 [%0], {%1, %2, %3, %4};"
                 :: "l"(p), "f"(v.x), "f"(v.y), "f"(v.z), "f"(v.w) : "memory");
}

// ------------------------------ prep kernels --------------------------------
__global__ void zero_agg_kernel() {
    size_t i = (size_t)blockIdx.x * blockDim.x + threadIdx.x;
    reinterpret_cast<float4*>(g_agg)[i] = make_float4(0.f, 0.f, 0.f, 0.f);
}
__global__ void prep_kernel(const float* __restrict__ eW1, const float* __restrict__ eW2,
                            const float* __restrict__ nW1, const float* __restrict__ nW2) {
    int i = blockIdx.x * blockDim.x + threadIdx.x;
    if (i < 98304)       g_W1e[i]          = totf(eW1[i]);
    else if (i < 131072) g_W2e[i - 98304]  = totf(eW2[i - 98304]);
    else if (i < 196608) g_W1n[i - 131072] = totf(nW1[i - 131072]);
    else if (i < 229376) g_W2n[i - 196608] = totf(nW2[i - 196608]);
}

// ------------------------------ edge kernel ---------------------------------
__global__ void __launch_bounds__(NTHR, 2)
edge_kernel(const float* __restrict__ efeat, const float* __restrict__ gridf,
            const float* __restrict__ mesh, const int* __restrict__ src,
            const int* __restrict__ dst,
            const float* __restrict__ b1, const float* __restrict__ b2,
            const float* __restrict__ gam, const float* __restrict__ bet)
{
    extern __shared__ float sm[];
    const uint32_t sb4 = smem_u32(sm);
    const int tid  = threadIdx.x;
    const int warp = tid >> 5, lane = tid & 31;
    const int e0 = blockIdx.x * MT;

    if (tid < 64) ((float4*)(sm + S_B1f))[tid] = ((const float4*)b1)[tid];
    else if (tid < 96)  ((float4*)(sm + S_B2f))[tid - 64] = ((const float4*)b2)[tid - 64];
    else if (tid < 128) ((float4*)(sm + S_Gf ))[tid - 96] = ((const float4*)gam)[tid - 96];
    if (tid < 32) ((float4*)(sm + S_BTf))[tid] = ((const float4*)bet)[tid];

    // gather: 2 threads per row, 16 cols each
    const int r  = tid >> 1;
    const int cb = (tid & 1) * 16;
    const int sidx = __ldg(&src[e0 + r]);
    const int didx = __ldg(&dst[e0 + r]);
    const float* rowE = efeat + (size_t)(e0 + r) * 128;
    const float* rowM = mesh  + (size_t)sidx * 128;
    const float* rowG = gridf + (size_t)didx * 128;

    auto stageA = [&](int c) {
        float* ab = sm + S_A0f + (c & 1) * (MT * LDA);
        const float* rp = (c < 4) ? rowE : (c < 8) ? rowM : rowG;
        const float4* gp = (const float4*)(rp + (c & 3) * 32 + cb);
        float* d = ab + r * LDA + cb;
        #pragma unroll
        for (int q = 0; q < 4; ++q) {
            float4 v = __ldg(gp + q);
            d[q*4+0] = totf(v.x); d[q*4+1] = totf(v.y);
            d[q*4+2] = totf(v.z); d[q*4+3] = totf(v.w);
        }
    };
    auto stageB1 = [&](int c) {
        uint32_t bb = sb4 + (uint32_t)(S_B0f + (c & 1) * (32 * LDB1)) * 4;
        const float* gw = g_W1e + c * 32 * 256;
        #pragma unroll
        for (int i = 0; i < 16; ++i) {
            int id = tid + NTHR * i; int rw = id >> 6, c16 = id & 63;
            cpa16(bb + (uint32_t)(rw * LDB1 + c16 * 4) * 4, gw + rw * 256 + c16 * 4);
        }
    };
    auto stageB2 = [&](int c) {
        uint32_t bb = sb4 + (uint32_t)(S_B20f + (c & 1) * (32 * LDB2)) * 4;
        const float* gw = g_W2e + c * 32 * 128;
        #pragma unroll
        for (int i = 0; i < 8; ++i) {
            int id = tid + NTHR * i; int rw = id >> 5, c16 = id & 31;
            cpa16(bb + (uint32_t)(rw * LDB2 + c16 * 4) * 4, gw + rw * 128 + c16 * 4);
        }
    };

    // ---------------- GEMM1: warp tile 64x64, acc[4][4] ----------------
    wmma::fragment<wmma::accumulator, 16, 16, 8, float> acc[4][4];
    #pragma unroll
    for (int i = 0; i < 4; i++)
        #pragma unroll
        for (int j = 0; j < 4; j++) wmma::fill_fragment(acc[i][j], 0.f);

    stageA(0); stageB1(0);
    cp_commit(); cp_wait0(); __syncthreads();

    #pragma unroll 1
    for (int c = 0; c < 12; ++c) {
        if (c + 1 < 12) { stageA(c + 1); stageB1(c + 1); }
        cp_commit();
        const float* ab = sm + S_A0f + (c & 1) * (MT * LDA);
        const float* bb = sm + S_B0f + (c & 1) * (32 * LDB1);
        #pragma unroll
        for (int kk = 0; kk < 32; kk += 8) {
            wmma::fragment<wmma::matrix_a, 16, 16, 8, wmma::precision::tf32, wmma::row_major> a[4];
            #pragma unroll
            for (int i = 0; i < 4; i++)
                wmma::load_matrix_sync(a[i], ab + (i * 16) * LDA + kk, LDA);
            #pragma unroll
            for (int j = 0; j < 4; j++) {
                wmma::fragment<wmma::matrix_b, 16, 16, 8, wmma::precision::tf32, wmma::row_major> b;
                wmma::load_matrix_sync(b, bb + kk * LDB1 + warp * 64 + j * 16, LDB1);
                #pragma unroll
                for (int i = 0; i < 4; i++)
                    wmma::mma_sync(acc[i][j], a[i], b, acc[i][j]);
            }
        }
        cp_wait0();
        __syncthreads();
    }

    // store H, bias + SiLU (tf32-rounded in place)
    #pragma unroll
    for (int i = 0; i < 4; i++)
        #pragma unroll
        for (int j = 0; j < 4; j++)
            wmma::store_matrix_sync(sm + S_Hf + (i * 16) * LDH + warp * 64 + j * 16,
                                    acc[i][j], LDH, wmma::mem_row_major);
    __syncthreads();
    #pragma unroll
    for (int i = 0; i < 32; i++) {
        int f = tid + NTHR * i; int rr = f >> 6, c4 = f & 63;
        float* p = sm + S_Hf + rr * LDH + c4 * 4;
        float4 v = *reinterpret_cast<float4*>(p);
        float4 bb = *reinterpret_cast<const float4*>(sm + S_B1f + c4 * 4);
        float h0 = v.x + bb.x, h1 = v.y + bb.y, h2 = v.z + bb.z, h3 = v.w + bb.w;
        p[0] = totf(h0 / (1.f + __expf(-h0)));
        p[1] = totf(h1 / (1.f + __expf(-h1)));
        p[2] = totf(h2 / (1.f + __expf(-h2)));
        p[3] = totf(h3 / (1.f + __expf(-h3)));
    }
    stageB2(0);
    cp_commit(); cp_wait0(); __syncthreads();

    // ---------------- GEMM2: warp tile 64x32, acc2[4][2] ----------------
    wmma::fragment<wmma::accumulator, 16, 16, 8, float> acc2[4][2];
    #pragma unroll
    for (int i = 0; i < 4; i++)
        #pragma unroll
        for (int j = 0; j < 2; j++) wmma::fill_fragment(acc2[i][j], 0.f);

    #pragma unroll 1
    for (int c = 0; c < 8; ++c) {
        if (c + 1 < 8) stageB2(c + 1);
        cp_commit();
        const float* bb = sm + S_B20f + (c & 1) * (32 * LDB2);
        #pragma unroll
        for (int kk = 0; kk < 32; kk += 8) {
            wmma::fragment<wmma::matrix_a, 16, 16, 8, wmma::precision::tf32, wmma::row_major> a[4];
            #pragma unroll
            for (int i = 0; i < 4; i++)
                wmma::load_matrix_sync(a[i], sm + S_Hf + (i * 16) * LDH + c * 32 + kk, LDH);
            #pragma unroll
            for (int j = 0; j < 2; j++) {
                wmma::fragment<wmma::matrix_b, 16, 16, 8, wmma::precision::tf32, wmma::row_major> b;
                wmma::load_matrix_sync(b, bb + kk * LDB2 + warp * 32 + j * 16, LDB2);
                #pragma unroll
                for (int i = 0; i < 4; i++)
                    wmma::mma_sync(acc2[i][j], a[i], b, acc2[i][j]);
            }
        }
        cp_wait0();
        __syncthreads();
    }
    #pragma unroll
    for (int i = 0; i < 4; i++)
        #pragma unroll
        for (int j = 0; j < 2; j++)
            wmma::store_matrix_sync(sm + S_Yf + (i * 16) * LDY + warp * 32 + j * 16,
                                    acc2[i][j], LDY, wmma::mem_row_major);
    __syncthreads();

    // ---------------- +b2, LN, vector-red scatter ----------------
    float4 bb2 = *reinterpret_cast<const float4*>(sm + S_B2f + lane * 4);
    float4 gg  = *reinterpret_cast<const float4*>(sm + S_Gf  + lane * 4);
    float4 bt  = *reinterpret_cast<const float4*>(sm + S_BTf + lane * 4);
    #pragma unroll 1
    for (int i = 0; i < 16; i++) {
        int row = warp * 16 + i;
        float4 v = *reinterpret_cast<const float4*>(sm + S_Yf + row * LDY + lane * 4);
        v.x += bb2.x; v.y += bb2.y; v.z += bb2.z; v.w += bb2.w;
        float sum = v.x + v.y + v.z + v.w;
        float sq  = v.x * v.x + v.y * v.y + v.z * v.z + v.w * v.w;
        #pragma unroll
        for (int o = 16; o > 0; o >>= 1) {
            sum += __shfl_xor_sync(0xFFFFFFFFu, sum, o);
            sq  += __shfl_xor_sync(0xFFFFFFFFu, sq,  o);
        }
        float mean = sum * (1.f / 128.f);
        float rstd = rsqrtf(sq * (1.f / 128.f) - mean * mean + 1e-5f);
        int dn = __ldg(&dst[e0 + row]);
        float4 o;
        o.x = (v.x - mean) * rstd * gg.x + bt.x;
        o.y = (v.y - mean) * rstd * gg.y + bt.y;
        o.z = (v.z - mean) * rstd * gg.z + bt.z;
        o.w = (v.w - mean) * rstd * gg.w + bt.w;
        red_add_v4(g_agg + (size_t)dn * 128 + lane * 4, o);
    }
}

// ------------------------------ node kernel ---------------------------------
__global__ void __launch_bounds__(NTHR, 2)
node_kernel(const float* __restrict__ gridf,
            const float* __restrict__ b1, const float* __restrict__ b2,
            const float* __restrict__ gam, const float* __restrict__ bet,
            float* __restrict__ out)
{
    extern __shared__ float sm[];
    const uint32_t sb4 = smem_u32(sm);
    const int tid  = threadIdx.x;
    const int warp = tid >> 5, lane = tid & 31;
    const int n0 = blockIdx.x * MT;

    if (tid < 64) ((float4*)(sm + S_B1f))[tid] = ((const float4*)b1)[tid];
    else if (tid < 96)  ((float4*)(sm + S_B2f))[tid - 64] = ((const float4*)b2)[tid - 64];
    else if (tid < 128) ((float4*)(sm + S_Gf ))[tid - 96] = ((const float4*)gam)[tid - 96];
    if (tid < 32) ((float4*)(sm + S_BTf))[tid] = ((const float4*)bet)[tid];

    const int r  = tid >> 1;
    const int cb = (tid & 1) * 16;
    const float* rowA = g_agg + (size_t)(n0 + r) * 128;
    const float* rowG = gridf + (size_t)(n0 + r) * 128;

    auto stageA = [&](int c) {
        float* ab = sm + S_A0f + (c & 1) * (MT * LDA);
        const float* rp = (c < 4) ? rowA : rowG;
        const float4* gp = (const float4*)(rp + (c & 3) * 32 + cb);
        float* d = ab + r * LDA + cb;
        #pragma unroll
        for (int q = 0; q < 4; ++q) {
            float4 v = __ldg(gp + q);
            d[q*4+0] = totf(v.x); d[q*4+1] = totf(v.y);
            d[q*4+2] = totf(v.z); d[q*4+3] = totf(v.w);
        }
    };
    auto stageB1 = [&](int c) {
        uint32_t bb = sb4 + (uint32_t)(S_B0f + (c & 1) * (32 * LDB1)) * 4;
        const float* gw = g_W1n + c * 32 * 256;
        #pragma unroll
        for (int i = 0; i < 16; ++i) {
            int id = tid + NTHR * i; int rw = id >> 6, c16 = id & 63;
            cpa16(bb + (uint32_t)(rw * LDB1 + c16 * 4) * 4, gw + rw * 256 + c16 * 4);
        }
    };
    auto stageB2 = [&](int c) {
        uint32_t bb = sb4 + (uint32_t)(S_B20f + (c & 1) * (32 * LDB2)) * 4;
        const float* gw = g_W2n + c * 32 * 128;
        #pragma unroll
        for (int i = 0; i < 8; ++i) {
            int id = tid + NTHR * i; int rw = id >> 5, c16 = id & 31;
            cpa16(bb + (uint32_t)(rw * LDB2 + c16 * 4) * 4, gw + rw * 128 + c16 * 4);
        }
    };

    // ---------------- GEMM1 ----------------
    wmma::fragment<wmma::accumulator, 16, 16, 8, float> acc[4][4];
    #pragma unroll
    for (int i = 0; i < 4; i++)
        #pragma unroll
        for (int j = 0; j < 4; j++) wmma::fill_fragment(acc[i][j], 0.f);

    stageA(0); stageB1(0);
    cp_commit(); cp_wait0(); __syncthreads();

    #pragma unroll 1
    for (int c = 0; c < 8; ++c) {
        if (c + 1 < 8) { stageA(c + 1); stageB1(c + 1); }
        cp_commit();
        const float* ab = sm + S_A0f + (c & 1) * (MT * LDA);
        const float* bb = sm + S_B0f + (c & 1) * (32 * LDB1);
        #pragma unroll
        for (int kk = 0; kk < 32; kk += 8) {
            wmma::fragment<wmma::matrix_a, 16, 16, 8, wmma::precision::tf32, wmma::row_major> a[4];
            #pragma unroll
            for (int i = 0; i < 4; i++)
                wmma::load_matrix_sync(a[i], ab + (i * 16) * LDA + kk, LDA);
            #pragma unroll
            for (int j = 0; j < 4; j++) {
                wmma::fragment<wmma::matrix_b, 16, 16, 8, wmma::precision::tf32, wmma::row_major> b;
                wmma::load_matrix_sync(b, bb + kk * LDB1 + warp * 64 + j * 16, LDB1);
                #pragma unroll
                for (int i = 0; i < 4; i++)
                    wmma::mma_sync(acc[i][j], a[i], b, acc[i][j]);
            }
        }
        cp_wait0();
        __syncthreads();
    }

    #pragma unroll
    for (int i = 0; i < 4; i++)
        #pragma unroll
        for (int j = 0; j < 4; j++)
            wmma::store_matrix_sync(sm + S_Hf + (i * 16) * LDH + warp * 64 + j * 16,
                                    acc[i][j], LDH, wmma::mem_row_major);
    __syncthreads();
    #pragma unroll
    for (int i = 0; i < 32; i++) {
        int f = tid + NTHR * i; int rr = f >> 6, c4 = f & 63;
        float* p = sm + S_Hf + rr * LDH + c4 * 4;
        float4 v = *reinterpret_cast<float4*>(p);
        float4 bb = *reinterpret_cast<const float4*>(sm + S_B1f + c4 * 4);
        float h0 = v.x + bb.x, h1 = v.y + bb.y, h2 = v.z + bb.z, h3 = v.w + bb.w;
        p[0] = totf(h0 / (1.f + __expf(-h0)));
        p[1] = totf(h1 / (1.f + __expf(-h1)));
        p[2] = totf(h2 / (1.f + __expf(-h2)));
        p[3] = totf(h3 / (1.f + __expf(-h3)));
    }
    stageB2(0);
    cp_commit(); cp_wait0(); __syncthreads();

    // ---------------- GEMM2 ----------------
    wmma::fragment<wmma::accumulator, 16, 16, 8, float> acc2[4][2];
    #pragma unroll
    for (int i = 0; i < 4; i++)
        #pragma unroll
        for (int j = 0; j < 2; j++) wmma::fill_fragment(acc2[i][j], 0.f);

    #pragma unroll 1
    for (int c = 0; c < 8; ++c) {
        if (c + 1 < 8) stageB2(c + 1);
        cp_commit();
        const float* bb = sm + S_B20f + (c & 1) * (32 * LDB2);
        #pragma unroll
        for (int kk = 0; kk < 32; kk += 8) {
            wmma::fragment<wmma::matrix_a, 16, 16, 8, wmma::precision::tf32, wmma::row_major> a[4];
            #pragma unroll
            for (int i = 0; i < 4; i++)
                wmma::load_matrix_sync(a[i], sm + S_Hf + (i * 16) * LDH + c * 32 + kk, LDH);
            #pragma unroll
            for (int j = 0; j < 2; j++) {
                wmma::fragment<wmma::matrix_b, 16, 16, 8, wmma::precision::tf32, wmma::row_major> b;
                wmma::load_matrix_sync(b, bb + kk * LDB2 + warp * 32 + j * 16, LDB2);
                #pragma unroll
                for (int i = 0; i < 4; i++)
                    wmma::mma_sync(acc2[i][j], a[i], b, acc2[i][j]);
            }
        }
        cp_wait0();
        __syncthreads();
    }
    #pragma unroll
    for (int i = 0; i < 4; i++)
        #pragma unroll
        for (int j = 0; j < 2; j++)
            wmma::store_matrix_sync(sm + S_Yf + (i * 16) * LDY + warp * 32 + j * 16,
                                    acc2[i][j], LDY, wmma::mem_row_major);
    __syncthreads();

    // ---------------- +b2, LN, affine, +residual ----------------
    float4 bb2 = *reinterpret_cast<const float4*>(sm + S_B2f + lane * 4);
    float4 gg  = *reinterpret_cast<const float4*>(sm + S_Gf  + lane * 4);
    float4 bt  = *reinterpret_cast<const float4*>(sm + S_BTf + lane * 4);
    #pragma unroll 1
    for (int i = 0; i < 16; i++) {
        int row = warp * 16 + i;
        float4 v = *reinterpret_cast<const float4*>(sm + S_Yf + row * LDY + lane * 4);
        v.x += bb2.x; v.y += bb2.y; v.z += bb2.z; v.w += bb2.w;
        float sum = v.x + v.y + v.z + v.w;
        float sq  = v.x * v.x + v.y * v.y + v.z * v.z + v.w * v.w;
        #pragma unroll
        for (int o = 16; o > 0; o >>= 1) {
            sum += __shfl_xor_sync(0xFFFFFFFFu, sum, o);
            sq  += __shfl_xor_sync(0xFFFFFFFFu, sq,  o);
        }
        float mean = sum * (1.f / 128.f);
        float rstd = rsqrtf(sq * (1.f / 128.f) - mean * mean + 1e-5f);
        size_t base = (size_t)(n0 + row) * 128;
        float4 gv = __ldg((const float4*)(gridf + base) + lane);
        float4 o;
        o.x = (v.x - mean) * rstd * gg.x + bt.x + gv.x;
        o.y = (v.y - mean) * rstd * gg.y + bt.y + gv.y;
        o.z = (v.z - mean) * rstd * gg.z + bt.z + gv.z;
        o.w = (v.w - mean) * rstd * gg.w + bt.w + gv.w;
        *((float4*)(out + base) + lane) = o;
    }
}

// ------------------------------ launch --------------------------------------
extern "C" void kernel_launch(void* const* d_in, const int* in_sizes, int n_in,
                              void* d_out, int out_size)
{
    const float* efeat = (const float*)d_in[0];
    const float* gridf = (const float*)d_in[1];
    const float* mesh  = (const float*)d_in[2];
    const int*   src   = (const int*)d_in[3];
    const int*   dst   = (const int*)d_in[4];
    const float* eW1   = (const float*)d_in[5];
    const float* eb1   = (const float*)d_in[6];
    const float* eW2   = (const float*)d_in[7];
    const float* eb2   = (const float*)d_in[8];
    const float* eg    = (const float*)d_in[9];
    const float* ebeta = (const float*)d_in[10];
    const float* nW1   = (const float*)d_in[11];
    const float* nb1   = (const float*)d_in[12];
    const float* nW2   = (const float*)d_in[13];
    const float* nb2   = (const float*)d_in[14];
    const float* ng    = (const float*)d_in[15];
    const float* nbeta = (const float*)d_in[16];
    float* out = (float*)d_out;

    const size_t smem = SMEM_FLOATS * sizeof(float);  // 102,912 B
    cudaFuncSetAttribute(edge_kernel, cudaFuncAttributeMaxDynamicSharedMemorySize, (int)smem);
    cudaFuncSetAttribute(node_kernel, cudaFuncAttributeMaxDynamicSharedMemorySize, (int)smem);

    zero_agg_kernel<<<8192, 1024>>>();
    prep_kernel<<<896, 256>>>(eW1, eW2, nW1, nW2);
    edge_kernel<<<N_EDGE / MT, NTHR, smem>>>(efeat, gridf, mesh, src, dst,
                                             eb1, eb2, eg, ebeta);
    node_kernel<<<N_GRID / MT, NTHR, smem>>>(gridf, nb1, nb2, ng, nbeta, out);
}

// round 6
// speedup vs baseline: 3.5055x; 2.9016x over previous
#include <cuda_runtime.h>
#include <cuda_fp16.h>
#include <mma.h>
#include <cstdint>

using namespace nvcuda;

#define N_MESH 40962
#define N_GRID 262144
#define N_EDGE 786432

// ------------------------------ device scratch ------------------------------
__device__ float  g_agg[(size_t)N_GRID * 128];
__device__ __half g_W1e[384 * 256];   // [K][N], fp16-RN pre-rounded
__device__ __half g_W2e[256 * 128];
__device__ __half g_W1n[256 * 256];
__device__ __half g_W2n[256 * 128];

// ------------------------------ tiling --------------------------------------
// 64 rows/CTA, 256 threads (8 warps: 2M x 4N), 2 CTAs/SM.
#define MT    64
#define NTHR  256

// ------------------------------ smem layout (BYTE offsets) ------------------
// consts (fp32): b1 @0 (256f), b2 @1024 (128f), g @1536, bt @2048 -> 2560
#define SM_CONST_B1 0
#define SM_CONST_B2 1024
#define SM_CONST_G  1536
#define SM_CONST_BT 2048
#define SM_A(b)   (2560 + (b) * 5120)     // half, 64 x 40   (double buf)
#define SM_B1(b)  (12800 + (b) * 16896)   // half, 32 x 264  (double buf)
#define SM_HF     12800                   // float, 64 x 260 (66,560B) overlaps dead B1
#define SM_B2(b)  (12800 + (b) * 8704)    // half, 32 x 136  (inside dead HF)
#define SM_HH     79360                   // half, 64 x 264  (33,792B)
#define SM_Y      30208                   // float, 64 x 132 (inside dead HF)
#define SMEM_BYTES 113152                 // x2 CTAs = 226,304 <= 228KB/SM

#define LDA   40    // halves
#define LDB1  264   // halves
#define LDB2  136   // halves
#define LDHF  260   // floats
#define LDHH  264   // halves
#define LDY   132   // floats

// ------------------------------ helpers -------------------------------------
__device__ __forceinline__ uint32_t smem_u32(const void* p) {
    uint32_t a;
    asm("{ .reg .u64 t; cvta.to.shared.u64 t, %1; cvt.u32.u64 %0, t; }" : "=r"(a) : "l"(p));
    return a;
}
__device__ __forceinline__ void cpa16(uint32_t s, const void* g) {
    asm volatile("cp.async.cg.shared.global [%0], [%1], 16;" :: "r"(s), "l"(g) : "memory");
}
__device__ __forceinline__ void cp_commit() {
    asm volatile("cp.async.commit_group;" ::: "memory");
}
__device__ __forceinline__ void cp_wait0() {
    asm volatile("cp.async.wait_group 0;" ::: "memory");
}
__device__ __forceinline__ void red_add_v4(float* p, float4 v) {
    asm volatile("red.global.add.v4.f32 [%0], {%1, %2, %3, %4};"
                 :: "l"(p), "f"(v.x), "f"(v.y), "f"(v.z), "f"(v.w) : "memory");
}
__device__ __forceinline__ uint4 pack8h(float4 a, float4 b) {
    __half2 h0 = __floats2half2_rn(a.x, a.y);
    __half2 h1 = __floats2half2_rn(a.z, a.w);
    __half2 h2 = __floats2half2_rn(b.x, b.y);
    __half2 h3 = __floats2half2_rn(b.z, b.w);
    uint4 u;
    u.x = *reinterpret_cast<uint32_t*>(&h0);
    u.y = *reinterpret_cast<uint32_t*>(&h1);
    u.z = *reinterpret_cast<uint32_t*>(&h2);
    u.w = *reinterpret_cast<uint32_t*>(&h3);
    return u;
}

typedef wmma::fragment<wmma::matrix_a, 16, 16, 16, __half, wmma::row_major> AFrag;
typedef wmma::fragment<wmma::matrix_b, 16, 16, 16, __half, wmma::row_major> BFrag;
typedef wmma::fragment<wmma::accumulator, 16, 16, 16, float> CFrag;

// ------------------------------ prep kernels --------------------------------
__global__ void zero_agg_kernel() {
    size_t i = (size_t)blockIdx.x * blockDim.x + threadIdx.x;
    reinterpret_cast<float4*>(g_agg)[i] = make_float4(0.f, 0.f, 0.f, 0.f);
}
__global__ void prep_kernel(const float* __restrict__ eW1, const float* __restrict__ eW2,
                            const float* __restrict__ nW1, const float* __restrict__ nW2) {
    int i = blockIdx.x * blockDim.x + threadIdx.x;
    if (i < 98304)       g_W1e[i]          = __float2half_rn(eW1[i]);
    else if (i < 131072) g_W2e[i - 98304]  = __float2half_rn(eW2[i - 98304]);
    else if (i < 196608) g_W1n[i - 131072] = __float2half_rn(nW1[i - 131072]);
    else if (i < 229376) g_W2n[i - 196608] = __float2half_rn(nW2[i - 196608]);
}

// ------------------------------ edge kernel ---------------------------------
__global__ void __launch_bounds__(NTHR, 2)
edge_kernel(const float* __restrict__ efeat, const float* __restrict__ gridf,
            const float* __restrict__ mesh, const int* __restrict__ src,
            const int* __restrict__ dst,
            const float* __restrict__ b1, const float* __restrict__ b2,
            const float* __restrict__ gam, const float* __restrict__ bet)
{
    extern __shared__ char smc[];
    const uint32_t sb = smem_u32(smc);
    const int tid  = threadIdx.x;
    const int warp = tid >> 5, lane = tid & 31;
    const int wm = warp >> 2, wn = warp & 3;
    const int e0 = blockIdx.x * MT;

    if (tid < 64) ((float4*)(smc + SM_CONST_B1))[tid] = ((const float4*)b1)[tid];
    else if (tid < 96)  ((float4*)(smc + SM_CONST_B2))[tid - 64] = ((const float4*)b2)[tid - 64];
    else if (tid < 128) ((float4*)(smc + SM_CONST_G ))[tid - 96] = ((const float4*)gam)[tid - 96];
    else if (tid < 160) ((float4*)(smc + SM_CONST_BT))[tid - 128] = ((const float4*)bet)[tid - 128];

    // gather: 4 threads/row, 8 floats each
    const int r  = tid >> 2;
    const int cb = (tid & 3) * 8;
    const int sidx = __ldg(&src[e0 + r]);
    const int didx = __ldg(&dst[e0 + r]);
    const float* rowE = efeat + (size_t)(e0 + r) * 128;
    const float* rowM = mesh  + (size_t)sidx * 128;
    const float* rowG = gridf + (size_t)didx * 128;

    float4 v0, v1;                 // in-flight gather values (held across MMAs)
    auto ldgA = [&](int c) {
        const float* rp = (c < 4) ? rowE : (c < 8) ? rowM : rowG;
        const float4* gp = (const float4*)(rp + (c & 3) * 32 + cb);
        v0 = __ldg(gp); v1 = __ldg(gp + 1);
    };
    auto stsA = [&](int c) {
        *(uint4*)(smc + SM_A(c & 1) + (r * LDA + cb) * 2) = pack8h(v0, v1);
    };
    auto stageB1 = [&](int c) {
        uint32_t bb = sb + SM_B1(c & 1);
        const __half* gw = g_W1e + c * 32 * 256;
        #pragma unroll
        for (int i = 0; i < 4; ++i) {
            int id = tid + NTHR * i; int rw = id >> 5, c16 = id & 31;
            cpa16(bb + (uint32_t)(rw * LDB1 + c16 * 8) * 2, gw + rw * 256 + c16 * 8);
        }
    };
    auto stageB2 = [&](int c) {
        uint32_t bb = sb + SM_B2(c & 1);
        const __half* gw = g_W2e + c * 32 * 128;
        #pragma unroll
        for (int i = 0; i < 2; ++i) {
            int id = tid + NTHR * i; int rw = id >> 4, c16 = id & 15;
            cpa16(bb + (uint32_t)(rw * LDB2 + c16 * 8) * 2, gw + rw * 128 + c16 * 8);
        }
    };

    // ---------------- GEMM1: [64,384]x[384,256], 12 K-chunks ----------------
    CFrag acc[2][4];
    #pragma unroll
    for (int i = 0; i < 2; i++)
        #pragma unroll
        for (int j = 0; j < 4; j++) wmma::fill_fragment(acc[i][j], 0.f);

    ldgA(0); stageB1(0); cp_commit(); stsA(0);
    cp_wait0(); __syncthreads();

    #pragma unroll 1
    for (int c = 0; c < 12; ++c) {
        if (c + 1 < 12) { ldgA(c + 1); stageB1(c + 1); }
        cp_commit();
        const __half* ab = (const __half*)(smc + SM_A(c & 1));
        const __half* bb = (const __half*)(smc + SM_B1(c & 1));
        #pragma unroll
        for (int kk = 0; kk < 32; kk += 16) {
            AFrag a0, a1;
            wmma::load_matrix_sync(a0, ab + (wm * 32)      * LDA + kk, LDA);
            wmma::load_matrix_sync(a1, ab + (wm * 32 + 16) * LDA + kk, LDA);
            #pragma unroll
            for (int j = 0; j < 4; j++) {
                BFrag b;
                wmma::load_matrix_sync(b, bb + kk * LDB1 + wn * 64 + j * 16, LDB1);
                wmma::mma_sync(acc[0][j], a0, b, acc[0][j]);
                wmma::mma_sync(acc[1][j], a1, b, acc[1][j]);
            }
        }
        if (c + 1 < 12) stsA(c + 1);
        cp_wait0();
        __syncthreads();
    }

    // acc -> HF (fp32), then bias+SiLU -> HH (fp16)
    float* hf = (float*)(smc + SM_HF);
    #pragma unroll
    for (int i = 0; i < 2; i++)
        #pragma unroll
        for (int j = 0; j < 4; j++)
            wmma::store_matrix_sync(hf + (wm * 32 + i * 16) * LDHF + wn * 64 + j * 16,
                                    acc[i][j], LDHF, wmma::mem_row_major);
    __syncthreads();
    {
        const float* sb1 = (const float*)(smc + SM_CONST_B1);
        #pragma unroll
        for (int i = 0; i < 8; i++) {
            int f = tid + NTHR * i;           // 0..2047
            int rr = f >> 5, c8 = (f & 31) * 8;
            const float* p = hf + rr * LDHF + c8;
            float4 x0 = *(const float4*)(p);
            float4 x1 = *(const float4*)(p + 4);
            float4 bb0 = *(const float4*)(sb1 + c8);
            float4 bb1 = *(const float4*)(sb1 + c8 + 4);
            x0.x += bb0.x; x0.y += bb0.y; x0.z += bb0.z; x0.w += bb0.w;
            x1.x += bb1.x; x1.y += bb1.y; x1.z += bb1.z; x1.w += bb1.w;
            float4 s0, s1;
            s0.x = x0.x / (1.f + __expf(-x0.x)); s0.y = x0.y / (1.f + __expf(-x0.y));
            s0.z = x0.z / (1.f + __expf(-x0.z)); s0.w = x0.w / (1.f + __expf(-x0.w));
            s1.x = x1.x / (1.f + __expf(-x1.x)); s1.y = x1.y / (1.f + __expf(-x1.y));
            s1.z = x1.z / (1.f + __expf(-x1.z)); s1.w = x1.w / (1.f + __expf(-x1.w));
            *(uint4*)(smc + SM_HH + (rr * LDHH + c8) * 2) = pack8h(s0, s1);
        }
    }
    __syncthreads();
    stageB2(0); cp_commit(); cp_wait0(); __syncthreads();

    // ---------------- GEMM2: [64,256]x[256,128], 8 K-chunks ----------------
    CFrag acc2[2][2];
    #pragma unroll
    for (int i = 0; i < 2; i++)
        #pragma unroll
        for (int j = 0; j < 2; j++) wmma::fill_fragment(acc2[i][j], 0.f);

    const __half* hh = (const __half*)(smc + SM_HH);
    #pragma unroll 1
    for (int c = 0; c < 8; ++c) {
        if (c + 1 < 8) stageB2(c + 1);
        cp_commit();
        const __half* bb = (const __half*)(smc + SM_B2(c & 1));
        #pragma unroll
        for (int kk = 0; kk < 32; kk += 16) {
            AFrag a0, a1;
            wmma::load_matrix_sync(a0, hh + (wm * 32)      * LDHH + c * 32 + kk, LDHH);
            wmma::load_matrix_sync(a1, hh + (wm * 32 + 16) * LDHH + c * 32 + kk, LDHH);
            #pragma unroll
            for (int j = 0; j < 2; j++) {
                BFrag b;
                wmma::load_matrix_sync(b, bb + kk * LDB2 + wn * 32 + j * 16, LDB2);
                wmma::mma_sync(acc2[0][j], a0, b, acc2[0][j]);
                wmma::mma_sync(acc2[1][j], a1, b, acc2[1][j]);
            }
        }
        cp_wait0();
        __syncthreads();
    }
    float* yf = (float*)(smc + SM_Y);
    #pragma unroll
    for (int i = 0; i < 2; i++)
        #pragma unroll
        for (int j = 0; j < 2; j++)
            wmma::store_matrix_sync(yf + (wm * 32 + i * 16) * LDY + wn * 32 + j * 16,
                                    acc2[i][j], LDY, wmma::mem_row_major);
    __syncthreads();

    // ---------------- +b2, LN, vector-red scatter ----------------
    float4 bb2 = *(const float4*)(smc + SM_CONST_B2 + lane * 16);
    float4 gg  = *(const float4*)(smc + SM_CONST_G  + lane * 16);
    float4 bt  = *(const float4*)(smc + SM_CONST_BT + lane * 16);
    #pragma unroll 1
    for (int i = 0; i < 8; i++) {
        int row = warp * 8 + i;
        float4 v = *(const float4*)(yf + row * LDY + lane * 4);
        v.x += bb2.x; v.y += bb2.y; v.z += bb2.z; v.w += bb2.w;
        float sum = v.x + v.y + v.z + v.w;
        float sq  = v.x * v.x + v.y * v.y + v.z * v.z + v.w * v.w;
        #pragma unroll
        for (int o = 16; o > 0; o >>= 1) {
            sum += __shfl_xor_sync(0xFFFFFFFFu, sum, o);
            sq  += __shfl_xor_sync(0xFFFFFFFFu, sq,  o);
        }
        float mean = sum * (1.f / 128.f);
        float rstd = rsqrtf(sq * (1.f / 128.f) - mean * mean + 1e-5f);
        int dn = __ldg(&dst[e0 + row]);
        float4 o;
        o.x = (v.x - mean) * rstd * gg.x + bt.x;
        o.y = (v.y - mean) * rstd * gg.y + bt.y;
        o.z = (v.z - mean) * rstd * gg.z + bt.z;
        o.w = (v.w - mean) * rstd * gg.w + bt.w;
        red_add_v4(g_agg + (size_t)dn * 128 + lane * 4, o);
    }
}

// ------------------------------ node kernel ---------------------------------
__global__ void __launch_bounds__(NTHR, 2)
node_kernel(const float* __restrict__ gridf,
            const float* __restrict__ b1, const float* __restrict__ b2,
            const float* __restrict__ gam, const float* __restrict__ bet,
            float* __restrict__ out)
{
    extern __shared__ char smc[];
    const uint32_t sb = smem_u32(smc);
    const int tid  = threadIdx.x;
    const int warp = tid >> 5, lane = tid & 31;
    const int wm = warp >> 2, wn = warp & 3;
    const int n0 = blockIdx.x * MT;

    if (tid < 64) ((float4*)(smc + SM_CONST_B1))[tid] = ((const float4*)b1)[tid];
    else if (tid < 96)  ((float4*)(smc + SM_CONST_B2))[tid - 64] = ((const float4*)b2)[tid - 64];
    else if (tid < 128) ((float4*)(smc + SM_CONST_G ))[tid - 96] = ((const float4*)gam)[tid - 96];
    else if (tid < 160) ((float4*)(smc + SM_CONST_BT))[tid - 128] = ((const float4*)bet)[tid - 128];

    const int r  = tid >> 2;
    const int cb = (tid & 3) * 8;
    const float* rowA = g_agg + (size_t)(n0 + r) * 128;
    const float* rowG = gridf + (size_t)(n0 + r) * 128;

    float4 v0, v1;
    auto ldgA = [&](int c) {
        const float* rp = (c < 4) ? rowA : rowG;
        const float4* gp = (const float4*)(rp + (c & 3) * 32 + cb);
        v0 = __ldg(gp); v1 = __ldg(gp + 1);
    };
    auto stsA = [&](int c) {
        *(uint4*)(smc + SM_A(c & 1) + (r * LDA + cb) * 2) = pack8h(v0, v1);
    };
    auto stageB1 = [&](int c) {
        uint32_t bb = sb + SM_B1(c & 1);
        const __half* gw = g_W1n + c * 32 * 256;
        #pragma unroll
        for (int i = 0; i < 4; ++i) {
            int id = tid + NTHR * i; int rw = id >> 5, c16 = id & 31;
            cpa16(bb + (uint32_t)(rw * LDB1 + c16 * 8) * 2, gw + rw * 256 + c16 * 8);
        }
    };
    auto stageB2 = [&](int c) {
        uint32_t bb = sb + SM_B2(c & 1);
        const __half* gw = g_W2n + c * 32 * 128;
        #pragma unroll
        for (int i = 0; i < 2; ++i) {
            int id = tid + NTHR * i; int rw = id >> 4, c16 = id & 15;
            cpa16(bb + (uint32_t)(rw * LDB2 + c16 * 8) * 2, gw + rw * 128 + c16 * 8);
        }
    };

    // ---------------- GEMM1: [64,256]x[256,256], 8 K-chunks ----------------
    CFrag acc[2][4];
    #pragma unroll
    for (int i = 0; i < 2; i++)
        #pragma unroll
        for (int j = 0; j < 4; j++) wmma::fill_fragment(acc[i][j], 0.f);

    ldgA(0); stageB1(0); cp_commit(); stsA(0);
    cp_wait0(); __syncthreads();

    #pragma unroll 1
    for (int c = 0; c < 8; ++c) {
        if (c + 1 < 8) { ldgA(c + 1); stageB1(c + 1); }
        cp_commit();
        const __half* ab = (const __half*)(smc + SM_A(c & 1));
        const __half* bb = (const __half*)(smc + SM_B1(c & 1));
        #pragma unroll
        for (int kk = 0; kk < 32; kk += 16) {
            AFrag a0, a1;
            wmma::load_matrix_sync(a0, ab + (wm * 32)      * LDA + kk, LDA);
            wmma::load_matrix_sync(a1, ab + (wm * 32 + 16) * LDA + kk, LDA);
            #pragma unroll
            for (int j = 0; j < 4; j++) {
                BFrag b;
                wmma::load_matrix_sync(b, bb + kk * LDB1 + wn * 64 + j * 16, LDB1);
                wmma::mma_sync(acc[0][j], a0, b, acc[0][j]);
                wmma::mma_sync(acc[1][j], a1, b, acc[1][j]);
            }
        }
        if (c + 1 < 8) stsA(c + 1);
        cp_wait0();
        __syncthreads();
    }

    float* hf = (float*)(smc + SM_HF);
    #pragma unroll
    for (int i = 0; i < 2; i++)
        #pragma unroll
        for (int j = 0; j < 4; j++)
            wmma::store_matrix_sync(hf + (wm * 32 + i * 16) * LDHF + wn * 64 + j * 16,
                                    acc[i][j], LDHF, wmma::mem_row_major);
    __syncthreads();
    {
        const float* sb1 = (const float*)(smc + SM_CONST_B1);
        #pragma unroll
        for (int i = 0; i < 8; i++) {
            int f = tid + NTHR * i;
            int rr = f >> 5, c8 = (f & 31) * 8;
            const float* p = hf + rr * LDHF + c8;
            float4 x0 = *(const float4*)(p);
            float4 x1 = *(const float4*)(p + 4);
            float4 bb0 = *(const float4*)(sb1 + c8);
            float4 bb1 = *(const float4*)(sb1 + c8 + 4);
            x0.x += bb0.x; x0.y += bb0.y; x0.z += bb0.z; x0.w += bb0.w;
            x1.x += bb1.x; x1.y += bb1.y; x1.z += bb1.z; x1.w += bb1.w;
            float4 s0, s1;
            s0.x = x0.x / (1.f + __expf(-x0.x)); s0.y = x0.y / (1.f + __expf(-x0.y));
            s0.z = x0.z / (1.f + __expf(-x0.z)); s0.w = x0.w / (1.f + __expf(-x0.w));
            s1.x = x1.x / (1.f + __expf(-x1.x)); s1.y = x1.y / (1.f + __expf(-x1.y));
            s1.z = x1.z / (1.f + __expf(-x1.z)); s1.w = x1.w / (1.f + __expf(-x1.w));
            *(uint4*)(smc + SM_HH + (rr * LDHH + c8) * 2) = pack8h(s0, s1);
        }
    }
    __syncthreads();
    stageB2(0); cp_commit(); cp_wait0(); __syncthreads();

    // ---------------- GEMM2 ----------------
    CFrag acc2[2][2];
    #pragma unroll
    for (int i = 0; i < 2; i++)
        #pragma unroll
        for (int j = 0; j < 2; j++) wmma::fill_fragment(acc2[i][j], 0.f);

    const __half* hh = (const __half*)(smc + SM_HH);
    #pragma unroll 1
    for (int c = 0; c < 8; ++c) {
        if (c + 1 < 8) stageB2(c + 1);
        cp_commit();
        const __half* bb = (const __half*)(smc + SM_B2(c & 1));
        #pragma unroll
        for (int kk = 0; kk < 32; kk += 16) {
            AFrag a0, a1;
            wmma::load_matrix_sync(a0, hh + (wm * 32)      * LDHH + c * 32 + kk, LDHH);
            wmma::load_matrix_sync(a1, hh + (wm * 32 + 16) * LDHH + c * 32 + kk, LDHH);
            #pragma unroll
            for (int j = 0; j < 2; j++) {
                BFrag b;
                wmma::load_matrix_sync(b, bb + kk * LDB2 + wn * 32 + j * 16, LDB2);
                wmma::mma_sync(acc2[0][j], a0, b, acc2[0][j]);
                wmma::mma_sync(acc2[1][j], a1, b, acc2[1][j]);
            }
        }
        cp_wait0();
        __syncthreads();
    }
    float* yf = (float*)(smc + SM_Y);
    #pragma unroll
    for (int i = 0; i < 2; i++)
        #pragma unroll
        for (int j = 0; j < 2; j++)
            wmma::store_matrix_sync(yf + (wm * 32 + i * 16) * LDY + wn * 32 + j * 16,
                                    acc2[i][j], LDY, wmma::mem_row_major);
    __syncthreads();

    // ---------------- +b2, LN, affine, +residual ----------------
    float4 bb2 = *(const float4*)(smc + SM_CONST_B2 + lane * 16);
    float4 gg  = *(const float4*)(smc + SM_CONST_G  + lane * 16);
    float4 bt  = *(const float4*)(smc + SM_CONST_BT + lane * 16);
    #pragma unroll 1
    for (int i = 0; i < 8; i++) {
        int row = warp * 8 + i;
        float4 v = *(const float4*)(yf + row * LDY + lane * 4);
        v.x += bb2.x; v.y += bb2.y; v.z += bb2.z; v.w += bb2.w;
        float sum = v.x + v.y + v.z + v.w;
        float sq  = v.x * v.x + v.y * v.y + v.z * v.z + v.w * v.w;
        #pragma unroll
        for (int o = 16; o > 0; o >>= 1) {
            sum += __shfl_xor_sync(0xFFFFFFFFu, sum, o);
            sq  += __shfl_xor_sync(0xFFFFFFFFu, sq,  o);
        }
        float mean = sum * (1.f / 128.f);
        float rstd = rsqrtf(sq * (1.f / 128.f) - mean * mean + 1e-5f);
        size_t base = (size_t)(n0 + row) * 128;
        float4 gv = __ldg((const float4*)(gridf + base) + lane);
        float4 o;
        o.x = (v.x - mean) * rstd * gg.x + bt.x + gv.x;
        o.y = (v.y - mean) * rstd * gg.y + bt.y + gv.y;
        o.z = (v.z - mean) * rstd * gg.z + bt.z + gv.z;
        o.w = (v.w - mean) * rstd * gg.w + bt.w + gv.w;
        *((float4*)(out + base) + lane) = o;
    }
}

// ------------------------------ launch --------------------------------------
extern "C" void kernel_launch(void* const* d_in, const int* in_sizes, int n_in,
                              void* d_out, int out_size)
{
    const float* efeat = (const float*)d_in[0];
    const float* gridf = (const float*)d_in[1];
    const float* mesh  = (const float*)d_in[2];
    const int*   src   = (const int*)d_in[3];
    const int*   dst   = (const int*)d_in[4];
    const float* eW1   = (const float*)d_in[5];
    const float* eb1   = (const float*)d_in[6];
    const float* eW2   = (const float*)d_in[7];
    const float* eb2   = (const float*)d_in[8];
    const float* eg    = (const float*)d_in[9];
    const float* ebeta = (const float*)d_in[10];
    const float* nW1   = (const float*)d_in[11];
    const float* nb1   = (const float*)d_in[12];
    const float* nW2   = (const float*)d_in[13];
    const float* nb2   = (const float*)d_in[14];
    const float* ng    = (const float*)d_in[15];
    const float* nbeta = (const float*)d_in[16];
    float* out = (float*)d_out;

    cudaFuncSetAttribute(edge_kernel, cudaFuncAttributeMaxDynamicSharedMemorySize, SMEM_BYTES);
    cudaFuncSetAttribute(node_kernel, cudaFuncAttributeMaxDynamicSharedMemorySize, SMEM_BYTES);

    zero_agg_kernel<<<8192, 1024>>>();
    prep_kernel<<<896, 256>>>(eW1, eW2, nW1, nW2);
    edge_kernel<<<N_EDGE / MT, NTHR, SMEM_BYTES>>>(efeat, gridf, mesh, src, dst,
                                                   eb1, eb2, eg, ebeta);
    node_kernel<<<N_GRID / MT, NTHR, SMEM_BYTES>>>(gridf, nb1, nb2, ng, nbeta, out);
}

// round 7
// speedup vs baseline: 3.7168x; 1.0603x over previous
#include <cuda_runtime.h>
#include <cuda_fp16.h>
#include <mma.h>
#include <cstdint>

using namespace nvcuda;

#define N_MESH 40962
#define N_GRID 262144
#define N_EDGE 786432

// ------------------------------ device scratch ------------------------------
__device__ float  g_agg[(size_t)N_GRID * 128];
__device__ __half g_W1e[384 * 256];   // [K][N], fp16-RN pre-rounded
__device__ __half g_W2e[256 * 128];
__device__ __half g_W1n[256 * 256];
__device__ __half g_W2n[256 * 128];

#define MT    64
#define NTHR  256

// ------------------------------ smem layout (BYTE offsets) ------------------
#define SM_CONST_B1 0
#define SM_CONST_B2 1024
#define SM_CONST_G  1536
#define SM_CONST_BT 2048
#define SM_A(b)    (2560 + (b) * 5120)     // half, 64 x 40, double buffer
#define SM_B1(s)   (12800 + (s) * 16896)   // half, 32 x 264, ring of 3
#define SM_B2(s)   (12800 + (s) * 8704)    // half, 32 x 136, ring of 3 (reuses B1)
#define SM_Y       38912                    // float, 64 x 132 (after B2 ring)
#define SM_SCR(w)  (63488 + (w) * 1280)    // float, 16 x 20 per-warp scratch
#define SM_HH      73728                    // half, 64 x 264
#define SMEM_BYTES 107520                   // x2 CTAs = 215,040 <= 227KB/SM

#define LDA   40    // halves
#define LDB1  264   // halves
#define LDB2  136   // halves
#define LDHH  264   // halves
#define LDY   132   // floats
#define LDSCR 20    // floats

// ------------------------------ helpers -------------------------------------
__device__ __forceinline__ uint32_t smem_u32(const void* p) {
    uint32_t a;
    asm("{ .reg .u64 t; cvta.to.shared.u64 t, %1; cvt.u32.u64 %0, t; }" : "=r"(a) : "l"(p));
    return a;
}
__device__ __forceinline__ void cpa16(uint32_t s, const void* g) {
    asm volatile("cp.async.cg.shared.global [%0], [%1], 16;" :: "r"(s), "l"(g) : "memory");
}
__device__ __forceinline__ void cp_commit() {
    asm volatile("cp.async.commit_group;" ::: "memory");
}
__device__ __forceinline__ void cp_wait1() {
    asm volatile("cp.async.wait_group 1;" ::: "memory");
}
__device__ __forceinline__ void red_add_v4(float* p, float4 v) {
    asm volatile("red.global.add.v4.f32 [%0], {%1, %2, %3, %4};"
                 :: "l"(p), "f"(v.x), "f"(v.y), "f"(v.z), "f"(v.w) : "memory");
}
__device__ __forceinline__ uint4 pack8h(float4 a, float4 b) {
    __half2 h0 = __floats2half2_rn(a.x, a.y);
    __half2 h1 = __floats2half2_rn(a.z, a.w);
    __half2 h2 = __floats2half2_rn(b.x, b.y);
    __half2 h3 = __floats2half2_rn(b.z, b.w);
    uint4 u;
    u.x = *reinterpret_cast<uint32_t*>(&h0);
    u.y = *reinterpret_cast<uint32_t*>(&h1);
    u.z = *reinterpret_cast<uint32_t*>(&h2);
    u.w = *reinterpret_cast<uint32_t*>(&h3);
    return u;
}
__device__ __forceinline__ float4 silu4(float4 x) {
    float4 s;
    s.x = x.x / (1.f + __expf(-x.x)); s.y = x.y / (1.f + __expf(-x.y));
    s.z = x.z / (1.f + __expf(-x.z)); s.w = x.w / (1.f + __expf(-x.w));
    return s;
}

typedef wmma::fragment<wmma::matrix_a, 16, 16, 16, __half, wmma::row_major> AFrag;
typedef wmma::fragment<wmma::matrix_b, 16, 16, 16, __half, wmma::row_major> BFrag;
typedef wmma::fragment<wmma::accumulator, 16, 16, 16, float> CFrag;

// ------------------------------ prep kernels --------------------------------
__global__ void zero_agg_kernel() {
    size_t i = (size_t)blockIdx.x * blockDim.x + threadIdx.x;
    reinterpret_cast<float4*>(g_agg)[i] = make_float4(0.f, 0.f, 0.f, 0.f);
}
__global__ void prep_kernel(const float* __restrict__ eW1, const float* __restrict__ eW2,
                            const float* __restrict__ nW1, const float* __restrict__ nW2) {
    int i = blockIdx.x * blockDim.x + threadIdx.x;
    if (i < 98304)       g_W1e[i]          = __float2half_rn(eW1[i]);
    else if (i < 131072) g_W2e[i - 98304]  = __float2half_rn(eW2[i - 98304]);
    else if (i < 196608) g_W1n[i - 131072] = __float2half_rn(nW1[i - 131072]);
    else if (i < 229376) g_W2n[i - 196608] = __float2half_rn(nW2[i - 196608]);
}

// ------------------------------ edge kernel ---------------------------------
__global__ void __launch_bounds__(NTHR, 2)
edge_kernel(const float* __restrict__ efeat, const float* __restrict__ gridf,
            const float* __restrict__ mesh, const int* __restrict__ src,
            const int* __restrict__ dst,
            const float* __restrict__ b1, const float* __restrict__ b2,
            const float* __restrict__ gam, const float* __restrict__ bet)
{
    extern __shared__ char smc[];
    const uint32_t sb = smem_u32(smc);
    const int tid  = threadIdx.x;
    const int warp = tid >> 5, lane = tid & 31;
    const int wm = warp >> 2, wn = warp & 3;
    const int e0 = blockIdx.x * MT;

    if (tid < 64) ((float4*)(smc + SM_CONST_B1))[tid] = ((const float4*)b1)[tid];
    else if (tid < 96)  ((float4*)(smc + SM_CONST_B2))[tid - 64] = ((const float4*)b2)[tid - 64];
    else if (tid < 128) ((float4*)(smc + SM_CONST_G ))[tid - 96] = ((const float4*)gam)[tid - 96];
    else if (tid < 160) ((float4*)(smc + SM_CONST_BT))[tid - 128] = ((const float4*)bet)[tid - 128];

    const int r  = tid >> 2;
    const int cb = (tid & 3) * 8;
    const int sidx = __ldg(&src[e0 + r]);
    const int didx = __ldg(&dst[e0 + r]);
    const float* rowE = efeat + (size_t)(e0 + r) * 128;
    const float* rowM = mesh  + (size_t)sidx * 128;
    const float* rowG = gridf + (size_t)didx * 128;

    float4 v0, v1;
    auto ldgA = [&](int c) {
        const float* rp = (c < 4) ? rowE : (c < 8) ? rowM : rowG;
        const float4* gp = (const float4*)(rp + (c & 3) * 32 + cb);
        v0 = __ldg(gp); v1 = __ldg(gp + 1);
    };
    auto stsA = [&](int c) {
        *(uint4*)(smc + SM_A(c & 1) + (r * LDA + cb) * 2) = pack8h(v0, v1);
    };
    auto stageB1 = [&](int c) {
        uint32_t bb = sb + SM_B1(c % 3);
        const __half* gw = g_W1e + c * 32 * 256;
        #pragma unroll
        for (int i = 0; i < 4; ++i) {
            int id = tid + NTHR * i; int rw = id >> 5, c16 = id & 31;
            cpa16(bb + (uint32_t)(rw * LDB1 + c16 * 8) * 2, gw + rw * 256 + c16 * 8);
        }
    };
    auto stageB2 = [&](int c) {
        uint32_t bb = sb + SM_B2(c % 3);
        const __half* gw = g_W2e + c * 32 * 128;
        #pragma unroll
        for (int i = 0; i < 2; ++i) {
            int id = tid + NTHR * i; int rw = id >> 4, c16 = id & 15;
            cpa16(bb + (uint32_t)(rw * LDB2 + c16 * 8) * 2, gw + rw * 128 + c16 * 8);
        }
    };

    // ---------------- GEMM1: [64,384]x[384,256], 12 K-chunks, ring-3 ----------
    CFrag acc[2][4];
    #pragma unroll
    for (int i = 0; i < 2; i++)
        #pragma unroll
        for (int j = 0; j < 4; j++) wmma::fill_fragment(acc[i][j], 0.f);

    ldgA(0);
    stageB1(0); cp_commit();
    stageB1(1); cp_commit();
    stsA(0);
    ldgA(1);

    #pragma unroll 1
    for (int c = 0; c < 12; ++c) {
        cp_wait1();          // B1(c) landed (requested 2 chunks ago)
        __syncthreads();     // A(c) STS visible; ring stage (c-1)%3 free
        if (c + 2 < 12) stageB1(c + 2);
        cp_commit();
        const __half* ab = (const __half*)(smc + SM_A(c & 1));
        const __half* bb = (const __half*)(smc + SM_B1(c % 3));
        #pragma unroll
        for (int kk = 0; kk < 32; kk += 16) {
            AFrag a0, a1;
            wmma::load_matrix_sync(a0, ab + (wm * 32)      * LDA + kk, LDA);
            wmma::load_matrix_sync(a1, ab + (wm * 32 + 16) * LDA + kk, LDA);
            #pragma unroll
            for (int j = 0; j < 4; j++) {
                BFrag b;
                wmma::load_matrix_sync(b, bb + kk * LDB1 + wn * 64 + j * 16, LDB1);
                wmma::mma_sync(acc[0][j], a0, b, acc[0][j]);
                wmma::mma_sync(acc[1][j], a1, b, acc[1][j]);
            }
        }
        if (c + 1 < 12) { stsA(c + 1); if (c + 2 < 12) ldgA(c + 2); }
    }
    __syncthreads();          // all GEMM1 MMAs done; B1 ring free for B2

    // prefetch GEMM2 weights while we do the SiLU transition
    stageB2(0); cp_commit();
    stageB2(1); cp_commit();

    // ---------------- transition: acc -> (bias,SiLU) -> HH fp16 --------------
    {
        float* scr = (float*)(smc + SM_SCR(warp));
        const float* sb1 = (const float*)(smc + SM_CONST_B1);
        const int rr = lane >> 1, ch = (lane & 1) * 8;
        #pragma unroll
        for (int i = 0; i < 2; i++)
            #pragma unroll
            for (int j = 0; j < 4; j++) {
                wmma::store_matrix_sync(scr, acc[i][j], LDSCR, wmma::mem_row_major);
                __syncwarp();
                const float* p = scr + rr * LDSCR + ch;
                float4 x0 = *(const float4*)(p);
                float4 x1 = *(const float4*)(p + 4);
                int cbase = wn * 64 + j * 16 + ch;
                float4 bb0 = *(const float4*)(sb1 + cbase);
                float4 bb1 = *(const float4*)(sb1 + cbase + 4);
                x0.x += bb0.x; x0.y += bb0.y; x0.z += bb0.z; x0.w += bb0.w;
                x1.x += bb1.x; x1.y += bb1.y; x1.z += bb1.z; x1.w += bb1.w;
                int rowg = wm * 32 + i * 16 + rr;
                *(uint4*)(smc + SM_HH + (rowg * LDHH + cbase) * 2) =
                    pack8h(silu4(x0), silu4(x1));
                __syncwarp();
            }
    }

    // ---------------- GEMM2: [64,256]x[256,128], 8 K-chunks, ring-3 ----------
    CFrag acc2[2][2];
    #pragma unroll
    for (int i = 0; i < 2; i++)
        #pragma unroll
        for (int j = 0; j < 2; j++) wmma::fill_fragment(acc2[i][j], 0.f);

    const __half* hh = (const __half*)(smc + SM_HH);
    #pragma unroll 1
    for (int c = 0; c < 8; ++c) {
        cp_wait1();
        __syncthreads();      // HH visible (c=0); B2 ring stage free
        if (c + 2 < 8) stageB2(c + 2);
        cp_commit();
        const __half* bb = (const __half*)(smc + SM_B2(c % 3));
        #pragma unroll
        for (int kk = 0; kk < 32; kk += 16) {
            AFrag a0, a1;
            wmma::load_matrix_sync(a0, hh + (wm * 32)      * LDHH + c * 32 + kk, LDHH);
            wmma::load_matrix_sync(a1, hh + (wm * 32 + 16) * LDHH + c * 32 + kk, LDHH);
            #pragma unroll
            for (int j = 0; j < 2; j++) {
                BFrag b;
                wmma::load_matrix_sync(b, bb + kk * LDB2 + wn * 32 + j * 16, LDB2);
                wmma::mma_sync(acc2[0][j], a0, b, acc2[0][j]);
                wmma::mma_sync(acc2[1][j], a1, b, acc2[1][j]);
            }
        }
    }
    float* yf = (float*)(smc + SM_Y);
    #pragma unroll
    for (int i = 0; i < 2; i++)
        #pragma unroll
        for (int j = 0; j < 2; j++)
            wmma::store_matrix_sync(yf + (wm * 32 + i * 16) * LDY + wn * 32 + j * 16,
                                    acc2[i][j], LDY, wmma::mem_row_major);
    __syncthreads();

    // ---------------- +b2, LN, vector-red scatter ----------------
    float4 bb2 = *(const float4*)(smc + SM_CONST_B2 + lane * 16);
    float4 gg  = *(const float4*)(smc + SM_CONST_G  + lane * 16);
    float4 bt  = *(const float4*)(smc + SM_CONST_BT + lane * 16);
    #pragma unroll 1
    for (int i = 0; i < 8; i++) {
        int row = warp * 8 + i;
        float4 v = *(const float4*)(yf + row * LDY + lane * 4);
        v.x += bb2.x; v.y += bb2.y; v.z += bb2.z; v.w += bb2.w;
        float sum = v.x + v.y + v.z + v.w;
        float sq  = v.x * v.x + v.y * v.y + v.z * v.z + v.w * v.w;
        #pragma unroll
        for (int o = 16; o > 0; o >>= 1) {
            sum += __shfl_xor_sync(0xFFFFFFFFu, sum, o);
            sq  += __shfl_xor_sync(0xFFFFFFFFu, sq,  o);
        }
        float mean = sum * (1.f / 128.f);
        float rstd = rsqrtf(sq * (1.f / 128.f) - mean * mean + 1e-5f);
        int dn = __ldg(&dst[e0 + row]);
        float4 o;
        o.x = (v.x - mean) * rstd * gg.x + bt.x;
        o.y = (v.y - mean) * rstd * gg.y + bt.y;
        o.z = (v.z - mean) * rstd * gg.z + bt.z;
        o.w = (v.w - mean) * rstd * gg.w + bt.w;
        red_add_v4(g_agg + (size_t)dn * 128 + lane * 4, o);
    }
}

// ------------------------------ node kernel ---------------------------------
__global__ void __launch_bounds__(NTHR, 2)
node_kernel(const float* __restrict__ gridf,
            const float* __restrict__ b1, const float* __restrict__ b2,
            const float* __restrict__ gam, const float* __restrict__ bet,
            float* __restrict__ out)
{
    extern __shared__ char smc[];
    const uint32_t sb = smem_u32(smc);
    const int tid  = threadIdx.x;
    const int warp = tid >> 5, lane = tid & 31;
    const int wm = warp >> 2, wn = warp & 3;
    const int n0 = blockIdx.x * MT;

    if (tid < 64) ((float4*)(smc + SM_CONST_B1))[tid] = ((const float4*)b1)[tid];
    else if (tid < 96)  ((float4*)(smc + SM_CONST_B2))[tid - 64] = ((const float4*)b2)[tid - 64];
    else if (tid < 128) ((float4*)(smc + SM_CONST_G ))[tid - 96] = ((const float4*)gam)[tid - 96];
    else if (tid < 160) ((float4*)(smc + SM_CONST_BT))[tid - 128] = ((const float4*)bet)[tid - 128];

    const int r  = tid >> 2;
    const int cb = (tid & 3) * 8;
    const float* rowA = g_agg + (size_t)(n0 + r) * 128;
    const float* rowG = gridf + (size_t)(n0 + r) * 128;

    float4 v0, v1;
    auto ldgA = [&](int c) {
        const float* rp = (c < 4) ? rowA : rowG;
        const float4* gp = (const float4*)(rp + (c & 3) * 32 + cb);
        v0 = __ldg(gp); v1 = __ldg(gp + 1);
    };
    auto stsA = [&](int c) {
        *(uint4*)(smc + SM_A(c & 1) + (r * LDA + cb) * 2) = pack8h(v0, v1);
    };
    auto stageB1 = [&](int c) {
        uint32_t bb = sb + SM_B1(c % 3);
        const __half* gw = g_W1n + c * 32 * 256;
        #pragma unroll
        for (int i = 0; i < 4; ++i) {
            int id = tid + NTHR * i; int rw = id >> 5, c16 = id & 31;
            cpa16(bb + (uint32_t)(rw * LDB1 + c16 * 8) * 2, gw + rw * 256 + c16 * 8);
        }
    };
    auto stageB2 = [&](int c) {
        uint32_t bb = sb + SM_B2(c % 3);
        const __half* gw = g_W2n + c * 32 * 128;
        #pragma unroll
        for (int i = 0; i < 2; ++i) {
            int id = tid + NTHR * i; int rw = id >> 4, c16 = id & 15;
            cpa16(bb + (uint32_t)(rw * LDB2 + c16 * 8) * 2, gw + rw * 128 + c16 * 8);
        }
    };

    // ---------------- GEMM1: [64,256]x[256,256], 8 K-chunks, ring-3 ----------
    CFrag acc[2][4];
    #pragma unroll
    for (int i = 0; i < 2; i++)
        #pragma unroll
        for (int j = 0; j < 4; j++) wmma::fill_fragment(acc[i][j], 0.f);

    ldgA(0);
    stageB1(0); cp_commit();
    stageB1(1); cp_commit();
    stsA(0);
    ldgA(1);

    #pragma unroll 1
    for (int c = 0; c < 8; ++c) {
        cp_wait1();
        __syncthreads();
        if (c + 2 < 8) stageB1(c + 2);
        cp_commit();
        const __half* ab = (const __half*)(smc + SM_A(c & 1));
        const __half* bb = (const __half*)(smc + SM_B1(c % 3));
        #pragma unroll
        for (int kk = 0; kk < 32; kk += 16) {
            AFrag a0, a1;
            wmma::load_matrix_sync(a0, ab + (wm * 32)      * LDA + kk, LDA);
            wmma::load_matrix_sync(a1, ab + (wm * 32 + 16) * LDA + kk, LDA);
            #pragma unroll
            for (int j = 0; j < 4; j++) {
                BFrag b;
                wmma::load_matrix_sync(b, bb + kk * LDB1 + wn * 64 + j * 16, LDB1);
                wmma::mma_sync(acc[0][j], a0, b, acc[0][j]);
                wmma::mma_sync(acc[1][j], a1, b, acc[1][j]);
            }
        }
        if (c + 1 < 8) { stsA(c + 1); if (c + 2 < 8) ldgA(c + 2); }
    }
    __syncthreads();

    stageB2(0); cp_commit();
    stageB2(1); cp_commit();

    // ---------------- transition: acc -> (bias,SiLU) -> HH fp16 --------------
    {
        float* scr = (float*)(smc + SM_SCR(warp));
        const float* sb1 = (const float*)(smc + SM_CONST_B1);
        const int rr = lane >> 1, ch = (lane & 1) * 8;
        #pragma unroll
        for (int i = 0; i < 2; i++)
            #pragma unroll
            for (int j = 0; j < 4; j++) {
                wmma::store_matrix_sync(scr, acc[i][j], LDSCR, wmma::mem_row_major);
                __syncwarp();
                const float* p = scr + rr * LDSCR + ch;
                float4 x0 = *(const float4*)(p);
                float4 x1 = *(const float4*)(p + 4);
                int cbase = wn * 64 + j * 16 + ch;
                float4 bb0 = *(const float4*)(sb1 + cbase);
                float4 bb1 = *(const float4*)(sb1 + cbase + 4);
                x0.x += bb0.x; x0.y += bb0.y; x0.z += bb0.z; x0.w += bb0.w;
                x1.x += bb1.x; x1.y += bb1.y; x1.z += bb1.z; x1.w += bb1.w;
                int rowg = wm * 32 + i * 16 + rr;
                *(uint4*)(smc + SM_HH + (rowg * LDHH + cbase) * 2) =
                    pack8h(silu4(x0), silu4(x1));
                __syncwarp();
            }
    }

    // ---------------- GEMM2: [64,256]x[256,128], 8 K-chunks, ring-3 ----------
    CFrag acc2[2][2];
    #pragma unroll
    for (int i = 0; i < 2; i++)
        #pragma unroll
        for (int j = 0; j < 2; j++) wmma::fill_fragment(acc2[i][j], 0.f);

    const __half* hh = (const __half*)(smc + SM_HH);
    #pragma unroll 1
    for (int c = 0; c < 8; ++c) {
        cp_wait1();
        __syncthreads();
        if (c + 2 < 8) stageB2(c + 2);
        cp_commit();
        const __half* bb = (const __half*)(smc + SM_B2(c % 3));
        #pragma unroll
        for (int kk = 0; kk < 32; kk += 16) {
            AFrag a0, a1;
            wmma::load_matrix_sync(a0, hh + (wm * 32)      * LDHH + c * 32 + kk, LDHH);
            wmma::load_matrix_sync(a1, hh + (wm * 32 + 16) * LDHH + c * 32 + kk, LDHH);
            #pragma unroll
            for (int j = 0; j < 2; j++) {
                BFrag b;
                wmma::load_matrix_sync(b, bb + kk * LDB2 + wn * 32 + j * 16, LDB2);
                wmma::mma_sync(acc2[0][j], a0, b, acc2[0][j]);
                wmma::mma_sync(acc2[1][j], a1, b, acc2[1][j]);
            }
        }
    }
    float* yf = (float*)(smc + SM_Y);
    #pragma unroll
    for (int i = 0; i < 2; i++)
        #pragma unroll
        for (int j = 0; j < 2; j++)
            wmma::store_matrix_sync(yf + (wm * 32 + i * 16) * LDY + wn * 32 + j * 16,
                                    acc2[i][j], LDY, wmma::mem_row_major);
    __syncthreads();

    // ---------------- +b2, LN, affine, +residual ----------------
    float4 bb2 = *(const float4*)(smc + SM_CONST_B2 + lane * 16);
    float4 gg  = *(const float4*)(smc + SM_CONST_G  + lane * 16);
    float4 bt  = *(const float4*)(smc + SM_CONST_BT + lane * 16);
    #pragma unroll 1
    for (int i = 0; i < 8; i++) {
        int row = warp * 8 + i;
        float4 v = *(const float4*)(yf + row * LDY + lane * 4);
        v.x += bb2.x; v.y += bb2.y; v.z += bb2.z; v.w += bb2.w;
        float sum = v.x + v.y + v.z + v.w;
        float sq  = v.x * v.x + v.y * v.y + v.z * v.z + v.w * v.w;
        #pragma unroll
        for (int o = 16; o > 0; o >>= 1) {
            sum += __shfl_xor_sync(0xFFFFFFFFu, sum, o);
            sq  += __shfl_xor_sync(0xFFFFFFFFu, sq,  o);
        }
        float mean = sum * (1.f / 128.f);
        float rstd = rsqrtf(sq * (1.f / 128.f) - mean * mean + 1e-5f);
        size_t base = (size_t)(n0 + row) * 128;
        float4 gv = __ldg((const float4*)(gridf + base) + lane);
        float4 o;
        o.x = (v.x - mean) * rstd * gg.x + bt.x + gv.x;
        o.y = (v.y - mean) * rstd * gg.y + bt.y + gv.y;
        o.z = (v.z - mean) * rstd * gg.z + bt.z + gv.z;
        o.w = (v.w - mean) * rstd * gg.w + bt.w + gv.w;
        *((float4*)(out + base) + lane) = o;
    }
}

// ------------------------------ launch --------------------------------------
extern "C" void kernel_launch(void* const* d_in, const int* in_sizes, int n_in,
                              void* d_out, int out_size)
{
    const float* efeat = (const float*)d_in[0];
    const float* gridf = (const float*)d_in[1];
    const float* mesh  = (const float*)d_in[2];
    const int*   src   = (const int*)d_in[3];
    const int*   dst   = (const int*)d_in[4];
    const float* eW1   = (const float*)d_in[5];
    const float* eb1   = (const float*)d_in[6];
    const float* eW2   = (const float*)d_in[7];
    const float* eb2   = (const float*)d_in[8];
    const float* eg    = (const float*)d_in[9];
    const float* ebeta = (const float*)d_in[10];
    const float* nW1   = (const float*)d_in[11];
    const float* nb1   = (const float*)d_in[12];
    const float* nW2   = (const float*)d_in[13];
    const float* nb2   = (const float*)d_in[14];
    const float* ng    = (const float*)d_in[15];
    const float* nbeta = (const float*)d_in[16];
    float* out = (float*)d_out;

    cudaFuncSetAttribute(edge_kernel, cudaFuncAttributeMaxDynamicSharedMemorySize, SMEM_BYTES);
    cudaFuncSetAttribute(node_kernel, cudaFuncAttributeMaxDynamicSharedMemorySize, SMEM_BYTES);

    zero_agg_kernel<<<8192, 1024>>>();
    prep_kernel<<<896, 256>>>(eW1, eW2, nW1, nW2);
    edge_kernel<<<N_EDGE / MT, NTHR, SMEM_BYTES>>>(efeat, gridf, mesh, src, dst,
                                                   eb1, eb2, eg, ebeta);
    node_kernel<<<N_GRID / MT, NTHR, SMEM_BYTES>>>(gridf, nb1, nb2, ng, nbeta, out);
}

// round 8
// speedup vs baseline: 3.7440x; 1.0073x over previous
#include <cuda_runtime.h>
#include <cuda_fp16.h>
#include <mma.h>
#include <cstdint>

using namespace nvcuda;

#define N_MESH 40962
#define N_GRID 262144
#define N_EDGE 786432

// ------------------------------ device scratch ------------------------------
__device__ float  g_agg[(size_t)N_GRID * 128];
__device__ __half g_W1e[384 * 256];   // [K][N], fp16-RN pre-rounded
__device__ __half g_W2e[256 * 128];
__device__ __half g_W1n[256 * 256];
__device__ __half g_W2n[256 * 128];

#define MT    64
#define NTHR  256

// ------------------------------ smem layout (BYTE offsets) ------------------
#define SM_CONST_B1 0
#define SM_CONST_B2 1024
#define SM_CONST_G  1536
#define SM_CONST_BT 2048
#define SM_A(b)    (2560 + (b) * 9216)      // half, 64 x 72, double buffer
#define SM_B1(s)   (20992 + (s) * 33792)    // half, 64 x 264, double buffer
#define SM_B2(s)   (20992 + (s) * 17408)    // half, 64 x 136, double (in B1 space)
#define SM_HH      55808                     // half, 64 x 264 (in dead B1 buf1)
#define SM_SCR(w)  (89600 + (w) * 1280)     // float, 16 x 20 per-warp scratch
#define SM_Y       20992                     // float, 64 x 132 (B2 dead by then)
#define SMEM_BYTES 99840                     // x2 CTAs = 199,680 <= 227KB/SM

#define LDA   72    // halves (stride 36 words mod 32 = 4 -> conflict-free 8-row)
#define LDB1  264   // halves
#define LDB2  136   // halves
#define LDHH  264   // halves
#define LDY   132   // floats
#define LDSCR 20    // floats

// ------------------------------ helpers -------------------------------------
__device__ __forceinline__ uint32_t smem_u32(const void* p) {
    uint32_t a;
    asm("{ .reg .u64 t; cvta.to.shared.u64 t, %1; cvt.u32.u64 %0, t; }" : "=r"(a) : "l"(p));
    return a;
}
__device__ __forceinline__ void cpa16(uint32_t s, const void* g) {
    asm volatile("cp.async.cg.shared.global [%0], [%1], 16;" :: "r"(s), "l"(g) : "memory");
}
__device__ __forceinline__ void cp_commit() {
    asm volatile("cp.async.commit_group;" ::: "memory");
}
__device__ __forceinline__ void cp_wait0() {
    asm volatile("cp.async.wait_group 0;" ::: "memory");
}
__device__ __forceinline__ void red_add_v4(float* p, float4 v) {
    asm volatile("red.global.add.v4.f32 [%0], {%1, %2, %3, %4};"
                 :: "l"(p), "f"(v.x), "f"(v.y), "f"(v.z), "f"(v.w) : "memory");
}
__device__ __forceinline__ uint4 pack8h(float4 a, float4 b) {
    __half2 h0 = __floats2half2_rn(a.x, a.y);
    __half2 h1 = __floats2half2_rn(a.z, a.w);
    __half2 h2 = __floats2half2_rn(b.x, b.y);
    __half2 h3 = __floats2half2_rn(b.z, b.w);
    uint4 u;
    u.x = *reinterpret_cast<uint32_t*>(&h0);
    u.y = *reinterpret_cast<uint32_t*>(&h1);
    u.z = *reinterpret_cast<uint32_t*>(&h2);
    u.w = *reinterpret_cast<uint32_t*>(&h3);
    return u;
}
__device__ __forceinline__ float4 silu4(float4 x) {
    float4 s;
    s.x = x.x / (1.f + __expf(-x.x)); s.y = x.y / (1.f + __expf(-x.y));
    s.z = x.z / (1.f + __expf(-x.z)); s.w = x.w / (1.f + __expf(-x.w));
    return s;
}

typedef wmma::fragment<wmma::matrix_a, 16, 16, 16, __half, wmma::row_major> AFrag;
typedef wmma::fragment<wmma::matrix_b, 16, 16, 16, __half, wmma::row_major> BFrag;
typedef wmma::fragment<wmma::accumulator, 16, 16, 16, float> CFrag;

// ------------------------------ prep kernels --------------------------------
__global__ void zero_agg_kernel() {
    size_t i = (size_t)blockIdx.x * blockDim.x + threadIdx.x;
    reinterpret_cast<float4*>(g_agg)[i] = make_float4(0.f, 0.f, 0.f, 0.f);
}
__global__ void prep_kernel(const float* __restrict__ eW1, const float* __restrict__ eW2,
                            const float* __restrict__ nW1, const float* __restrict__ nW2) {
    int i = blockIdx.x * blockDim.x + threadIdx.x;
    if (i < 98304)       g_W1e[i]          = __float2half_rn(eW1[i]);
    else if (i < 131072) g_W2e[i - 98304]  = __float2half_rn(eW2[i - 98304]);
    else if (i < 196608) g_W1n[i - 131072] = __float2half_rn(nW1[i - 131072]);
    else if (i < 229376) g_W2n[i - 196608] = __float2half_rn(nW2[i - 196608]);
}

// ------------------------------ edge kernel ---------------------------------
// tile = 64 edges; K-chunks of 64. GEMM1 6 chunks, GEMM2 4 chunks.
__global__ void __launch_bounds__(NTHR, 2)
edge_kernel(const float* __restrict__ efeat, const float* __restrict__ gridf,
            const float* __restrict__ mesh, const int* __restrict__ src,
            const int* __restrict__ dst,
            const float* __restrict__ b1, const float* __restrict__ b2,
            const float* __restrict__ gam, const float* __restrict__ bet)
{
    extern __shared__ char smc[];
    const uint32_t sb = smem_u32(smc);
    const int tid  = threadIdx.x;
    const int warp = tid >> 5, lane = tid & 31;
    const int wm = warp >> 2, wn = warp & 3;
    const int e0 = blockIdx.x * MT;

    if (tid < 64) ((float4*)(smc + SM_CONST_B1))[tid] = ((const float4*)b1)[tid];
    else if (tid < 96)  ((float4*)(smc + SM_CONST_B2))[tid - 64] = ((const float4*)b2)[tid - 64];
    else if (tid < 128) ((float4*)(smc + SM_CONST_G ))[tid - 96] = ((const float4*)gam)[tid - 96];
    else if (tid < 160) ((float4*)(smc + SM_CONST_BT))[tid - 128] = ((const float4*)bet)[tid - 128];

    // gather: 4 threads/row, 16 floats each
    const int r  = tid >> 2;
    const int cb = (tid & 3) * 16;
    const int sidx = __ldg(&src[e0 + r]);
    const int didx = __ldg(&dst[e0 + r]);
    const float* rowE = efeat + (size_t)(e0 + r) * 128;
    const float* rowM = mesh  + (size_t)sidx * 128;
    const float* rowG = gridf + (size_t)didx * 128;

    float4 v0, v1, v2, v3;
    auto ldgA = [&](int c) {
        const float* rp = (c < 2) ? rowE : (c < 4) ? rowM : rowG;
        const float4* gp = (const float4*)(rp + (c & 1) * 64 + cb);
        v0 = __ldg(gp); v1 = __ldg(gp + 1); v2 = __ldg(gp + 2); v3 = __ldg(gp + 3);
    };
    auto stsA = [&](int c) {
        char* d = smc + SM_A(c & 1) + (r * LDA + cb) * 2;
        *(uint4*)(d)      = pack8h(v0, v1);
        *(uint4*)(d + 16) = pack8h(v2, v3);
    };
    auto stageB1 = [&](int c) {
        uint32_t bb = sb + SM_B1(c & 1);
        const __half* gw = g_W1e + c * 64 * 256;
        #pragma unroll
        for (int i = 0; i < 8; ++i) {
            int id = tid + NTHR * i; int rw = id >> 5, c16 = id & 31;
            cpa16(bb + (uint32_t)(rw * LDB1 + c16 * 8) * 2, gw + rw * 256 + c16 * 8);
        }
    };
    auto stageB2 = [&](int c) {
        uint32_t bb = sb + SM_B2(c & 1);
        const __half* gw = g_W2e + c * 64 * 128;
        #pragma unroll
        for (int i = 0; i < 4; ++i) {
            int id = tid + NTHR * i; int rw = id >> 4, c16 = id & 15;
            cpa16(bb + (uint32_t)(rw * LDB2 + c16 * 8) * 2, gw + rw * 128 + c16 * 8);
        }
    };

    // ---------------- GEMM1: [64,384]x[384,256], 6 K64-chunks ----------------
    CFrag acc[2][4];
    #pragma unroll
    for (int i = 0; i < 2; i++)
        #pragma unroll
        for (int j = 0; j < 4; j++) wmma::fill_fragment(acc[i][j], 0.f);

    ldgA(0);
    stageB1(0); cp_commit();
    stsA(0);
    ldgA(1);

    #pragma unroll 1
    for (int c = 0; c < 6; ++c) {
        cp_wait0();           // B1(c) landed
        __syncthreads();      // A(c) visible; prior chunk's MMAs done everywhere
        if (c + 1 < 6) { stageB1(c + 1); cp_commit(); }
        const __half* ab = (const __half*)(smc + SM_A(c & 1));
        const __half* bb = (const __half*)(smc + SM_B1(c & 1));
        #pragma unroll
        for (int kk = 0; kk < 64; kk += 16) {
            AFrag a0, a1;
            wmma::load_matrix_sync(a0, ab + (wm * 32)      * LDA + kk, LDA);
            wmma::load_matrix_sync(a1, ab + (wm * 32 + 16) * LDA + kk, LDA);
            #pragma unroll
            for (int j = 0; j < 4; j++) {
                BFrag b;
                wmma::load_matrix_sync(b, bb + kk * LDB1 + wn * 64 + j * 16, LDB1);
                wmma::mma_sync(acc[0][j], a0, b, acc[0][j]);
                wmma::mma_sync(acc[1][j], a1, b, acc[1][j]);
            }
        }
        if (c + 1 < 6) { stsA(c + 1); if (c + 2 < 6) ldgA(c + 2); }
    }
    __syncthreads();          // all GEMM1 MMAs done chip-wide in CTA

    stageB2(0); cp_commit();  // prefetch GEMM2 chunk 0 behind the transition

    // ---------------- transition: acc -> (bias,SiLU) -> HH fp16 --------------
    {
        float* scr = (float*)(smc + SM_SCR(warp));
        const float* sb1 = (const float*)(smc + SM_CONST_B1);
        const int rr = lane >> 1, ch = (lane & 1) * 8;
        #pragma unroll
        for (int i = 0; i < 2; i++)
            #pragma unroll
            for (int j = 0; j < 4; j++) {
                wmma::store_matrix_sync(scr, acc[i][j], LDSCR, wmma::mem_row_major);
                __syncwarp();
                const float* p = scr + rr * LDSCR + ch;
                float4 x0 = *(const float4*)(p);
                float4 x1 = *(const float4*)(p + 4);
                int cbase = wn * 64 + j * 16 + ch;
                float4 bb0 = *(const float4*)(sb1 + cbase);
                float4 bb1 = *(const float4*)(sb1 + cbase + 4);
                x0.x += bb0.x; x0.y += bb0.y; x0.z += bb0.z; x0.w += bb0.w;
                x1.x += bb1.x; x1.y += bb1.y; x1.z += bb1.z; x1.w += bb1.w;
                int rowg = wm * 32 + i * 16 + rr;
                *(uint4*)(smc + SM_HH + (rowg * LDHH + cbase) * 2) =
                    pack8h(silu4(x0), silu4(x1));
                __syncwarp();
            }
    }

    // ---------------- GEMM2: [64,256]x[256,128], 4 K64-chunks ----------------
    CFrag acc2[2][2];
    #pragma unroll
    for (int i = 0; i < 2; i++)
        #pragma unroll
        for (int j = 0; j < 2; j++) wmma::fill_fragment(acc2[i][j], 0.f);

    const __half* hh = (const __half*)(smc + SM_HH);
    #pragma unroll 1
    for (int c = 0; c < 4; ++c) {
        cp_wait0();
        __syncthreads();      // HH visible (c=0); buffer (c+1)&1 free
        if (c + 1 < 4) { stageB2(c + 1); cp_commit(); }
        const __half* bb = (const __half*)(smc + SM_B2(c & 1));
        #pragma unroll
        for (int kk = 0; kk < 64; kk += 16) {
            AFrag a0, a1;
            wmma::load_matrix_sync(a0, hh + (wm * 32)      * LDHH + c * 64 + kk, LDHH);
            wmma::load_matrix_sync(a1, hh + (wm * 32 + 16) * LDHH + c * 64 + kk, LDHH);
            #pragma unroll
            for (int j = 0; j < 2; j++) {
                BFrag b;
                wmma::load_matrix_sync(b, bb + kk * LDB2 + wn * 32 + j * 16, LDB2);
                wmma::mma_sync(acc2[0][j], a0, b, acc2[0][j]);
                wmma::mma_sync(acc2[1][j], a1, b, acc2[1][j]);
            }
        }
    }
    __syncthreads();          // all GEMM2 MMAs done; B2 region reusable as Y
    float* yf = (float*)(smc + SM_Y);
    #pragma unroll
    for (int i = 0; i < 2; i++)
        #pragma unroll
        for (int j = 0; j < 2; j++)
            wmma::store_matrix_sync(yf + (wm * 32 + i * 16) * LDY + wn * 32 + j * 16,
                                    acc2[i][j], LDY, wmma::mem_row_major);
    __syncthreads();

    // ---------------- +b2, LN, vector-red scatter ----------------
    float4 bb2 = *(const float4*)(smc + SM_CONST_B2 + lane * 16);
    float4 gg  = *(const float4*)(smc + SM_CONST_G  + lane * 16);
    float4 bt  = *(const float4*)(smc + SM_CONST_BT + lane * 16);
    #pragma unroll 1
    for (int i = 0; i < 8; i++) {
        int row = warp * 8 + i;
        float4 v = *(const float4*)(yf + row * LDY + lane * 4);
        v.x += bb2.x; v.y += bb2.y; v.z += bb2.z; v.w += bb2.w;
        float sum = v.x + v.y + v.z + v.w;
        float sq  = v.x * v.x + v.y * v.y + v.z * v.z + v.w * v.w;
        #pragma unroll
        for (int o = 16; o > 0; o >>= 1) {
            sum += __shfl_xor_sync(0xFFFFFFFFu, sum, o);
            sq  += __shfl_xor_sync(0xFFFFFFFFu, sq,  o);
        }
        float mean = sum * (1.f / 128.f);
        float rstd = rsqrtf(sq * (1.f / 128.f) - mean * mean + 1e-5f);
        int dn = __ldg(&dst[e0 + row]);
        float4 o;
        o.x = (v.x - mean) * rstd * gg.x + bt.x;
        o.y = (v.y - mean) * rstd * gg.y + bt.y;
        o.z = (v.z - mean) * rstd * gg.z + bt.z;
        o.w = (v.w - mean) * rstd * gg.w + bt.w;
        red_add_v4(g_agg + (size_t)dn * 128 + lane * 4, o);
    }
}

// ------------------------------ node kernel ---------------------------------
__global__ void __launch_bounds__(NTHR, 2)
node_kernel(const float* __restrict__ gridf,
            const float* __restrict__ b1, const float* __restrict__ b2,
            const float* __restrict__ gam, const float* __restrict__ bet,
            float* __restrict__ out)
{
    extern __shared__ char smc[];
    const uint32_t sb = smem_u32(smc);
    const int tid  = threadIdx.x;
    const int warp = tid >> 5, lane = tid & 31;
    const int wm = warp >> 2, wn = warp & 3;
    const int n0 = blockIdx.x * MT;

    if (tid < 64) ((float4*)(smc + SM_CONST_B1))[tid] = ((const float4*)b1)[tid];
    else if (tid < 96)  ((float4*)(smc + SM_CONST_B2))[tid - 64] = ((const float4*)b2)[tid - 64];
    else if (tid < 128) ((float4*)(smc + SM_CONST_G ))[tid - 96] = ((const float4*)gam)[tid - 96];
    else if (tid < 160) ((float4*)(smc + SM_CONST_BT))[tid - 128] = ((const float4*)bet)[tid - 128];

    const int r  = tid >> 2;
    const int cb = (tid & 3) * 16;
    const float* rowA = g_agg + (size_t)(n0 + r) * 128;
    const float* rowG = gridf + (size_t)(n0 + r) * 128;

    float4 v0, v1, v2, v3;
    auto ldgA = [&](int c) {
        const float* rp = (c < 2) ? rowA : rowG;
        const float4* gp = (const float4*)(rp + (c & 1) * 64 + cb);
        v0 = __ldg(gp); v1 = __ldg(gp + 1); v2 = __ldg(gp + 2); v3 = __ldg(gp + 3);
    };
    auto stsA = [&](int c) {
        char* d = smc + SM_A(c & 1) + (r * LDA + cb) * 2;
        *(uint4*)(d)      = pack8h(v0, v1);
        *(uint4*)(d + 16) = pack8h(v2, v3);
    };
    auto stageB1 = [&](int c) {
        uint32_t bb = sb + SM_B1(c & 1);
        const __half* gw = g_W1n + c * 64 * 256;
        #pragma unroll
        for (int i = 0; i < 8; ++i) {
            int id = tid + NTHR * i; int rw = id >> 5, c16 = id & 31;
            cpa16(bb + (uint32_t)(rw * LDB1 + c16 * 8) * 2, gw + rw * 256 + c16 * 8);
        }
    };
    auto stageB2 = [&](int c) {
        uint32_t bb = sb + SM_B2(c & 1);
        const __half* gw = g_W2n + c * 64 * 128;
        #pragma unroll
        for (int i = 0; i < 4; ++i) {
            int id = tid + NTHR * i; int rw = id >> 4, c16 = id & 15;
            cpa16(bb + (uint32_t)(rw * LDB2 + c16 * 8) * 2, gw + rw * 128 + c16 * 8);
        }
    };

    // ---------------- GEMM1: [64,256]x[256,256], 4 K64-chunks ----------------
    CFrag acc[2][4];
    #pragma unroll
    for (int i = 0; i < 2; i++)
        #pragma unroll
        for (int j = 0; j < 4; j++) wmma::fill_fragment(acc[i][j], 0.f);

    ldgA(0);
    stageB1(0); cp_commit();
    stsA(0);
    ldgA(1);

    #pragma unroll 1
    for (int c = 0; c < 4; ++c) {
        cp_wait0();
        __syncthreads();
        if (c + 1 < 4) { stageB1(c + 1); cp_commit(); }
        const __half* ab = (const __half*)(smc + SM_A(c & 1));
        const __half* bb = (const __half*)(smc + SM_B1(c & 1));
        #pragma unroll
        for (int kk = 0; kk < 64; kk += 16) {
            AFrag a0, a1;
            wmma::load_matrix_sync(a0, ab + (wm * 32)      * LDA + kk, LDA);
            wmma::load_matrix_sync(a1, ab + (wm * 32 + 16) * LDA + kk, LDA);
            #pragma unroll
            for (int j = 0; j < 4; j++) {
                BFrag b;
                wmma::load_matrix_sync(b, bb + kk * LDB1 + wn * 64 + j * 16, LDB1);
                wmma::mma_sync(acc[0][j], a0, b, acc[0][j]);
                wmma::mma_sync(acc[1][j], a1, b, acc[1][j]);
            }
        }
        if (c + 1 < 4) { stsA(c + 1); if (c + 2 < 4) ldgA(c + 2); }
    }
    __syncthreads();

    stageB2(0); cp_commit();

    // ---------------- transition: acc -> (bias,SiLU) -> HH fp16 --------------
    {
        float* scr = (float*)(smc + SM_SCR(warp));
        const float* sb1 = (const float*)(smc + SM_CONST_B1);
        const int rr = lane >> 1, ch = (lane & 1) * 8;
        #pragma unroll
        for (int i = 0; i < 2; i++)
            #pragma unroll
            for (int j = 0; j < 4; j++) {
                wmma::store_matrix_sync(scr, acc[i][j], LDSCR, wmma::mem_row_major);
                __syncwarp();
                const float* p = scr + rr * LDSCR + ch;
                float4 x0 = *(const float4*)(p);
                float4 x1 = *(const float4*)(p + 4);
                int cbase = wn * 64 + j * 16 + ch;
                float4 bb0 = *(const float4*)(sb1 + cbase);
                float4 bb1 = *(const float4*)(sb1 + cbase + 4);
                x0.x += bb0.x; x0.y += bb0.y; x0.z += bb0.z; x0.w += bb0.w;
                x1.x += bb1.x; x1.y += bb1.y; x1.z += bb1.z; x1.w += bb1.w;
                int rowg = wm * 32 + i * 16 + rr;
                *(uint4*)(smc + SM_HH + (rowg * LDHH + cbase) * 2) =
                    pack8h(silu4(x0), silu4(x1));
                __syncwarp();
            }
    }

    // ---------------- GEMM2: [64,256]x[256,128], 4 K64-chunks ----------------
    CFrag acc2[2][2];
    #pragma unroll
    for (int i = 0; i < 2; i++)
        #pragma unroll
        for (int j = 0; j < 2; j++) wmma::fill_fragment(acc2[i][j], 0.f);

    const __half* hh = (const __half*)(smc + SM_HH);
    #pragma unroll 1
    for (int c = 0; c < 4; ++c) {
        cp_wait0();
        __syncthreads();
        if (c + 1 < 4) { stageB2(c + 1); cp_commit(); }
        const __half* bb = (const __half*)(smc + SM_B2(c & 1));
        #pragma unroll
        for (int kk = 0; kk < 64; kk += 16) {
            AFrag a0, a1;
            wmma::load_matrix_sync(a0, hh + (wm * 32)      * LDHH + c * 64 + kk, LDHH);
            wmma::load_matrix_sync(a1, hh + (wm * 32 + 16) * LDHH + c * 64 + kk, LDHH);
            #pragma unroll
            for (int j = 0; j < 2; j++) {
                BFrag b;
                wmma::load_matrix_sync(b, bb + kk * LDB2 + wn * 32 + j * 16, LDB2);
                wmma::mma_sync(acc2[0][j], a0, b, acc2[0][j]);
                wmma::mma_sync(acc2[1][j], a1, b, acc2[1][j]);
            }
        }
    }
    __syncthreads();
    float* yf = (float*)(smc + SM_Y);
    #pragma unroll
    for (int i = 0; i < 2; i++)
        #pragma unroll
        for (int j = 0; j < 2; j++)
            wmma::store_matrix_sync(yf + (wm * 32 + i * 16) * LDY + wn * 32 + j * 16,
                                    acc2[i][j], LDY, wmma::mem_row_major);
    __syncthreads();

    // ---------------- +b2, LN, affine, +residual ----------------
    float4 bb2 = *(const float4*)(smc + SM_CONST_B2 + lane * 16);
    float4 gg  = *(const float4*)(smc + SM_CONST_G  + lane * 16);
    float4 bt  = *(const float4*)(smc + SM_CONST_BT + lane * 16);
    #pragma unroll 1
    for (int i = 0; i < 8; i++) {
        int row = warp * 8 + i;
        float4 v = *(const float4*)(yf + row * LDY + lane * 4);
        v.x += bb2.x; v.y += bb2.y; v.z += bb2.z; v.w += bb2.w;
        float sum = v.x + v.y + v.z + v.w;
        float sq  = v.x * v.x + v.y * v.y + v.z * v.z + v.w * v.w;
        #pragma unroll
        for (int o = 16; o > 0; o >>= 1) {
            sum += __shfl_xor_sync(0xFFFFFFFFu, sum, o);
            sq  += __shfl_xor_sync(0xFFFFFFFFu, sq,  o);
        }
        float mean = sum * (1.f / 128.f);
        float rstd = rsqrtf(sq * (1.f / 128.f) - mean * mean + 1e-5f);
        size_t base = (size_t)(n0 + row) * 128;
        float4 gv = __ldg((const float4*)(gridf + base) + lane);
        float4 o;
        o.x = (v.x - mean) * rstd * gg.x + bt.x + gv.x;
        o.y = (v.y - mean) * rstd * gg.y + bt.y + gv.y;
        o.z = (v.z - mean) * rstd * gg.z + bt.z + gv.z;
        o.w = (v.w - mean) * rstd * gg.w + bt.w + gv.w;
        *((float4*)(out + base) + lane) = o;
    }
}

// ------------------------------ launch --------------------------------------
extern "C" void kernel_launch(void* const* d_in, const int* in_sizes, int n_in,
                              void* d_out, int out_size)
{
    const float* efeat = (const float*)d_in[0];
    const float* gridf = (const float*)d_in[1];
    const float* mesh  = (const float*)d_in[2];
    const int*   src   = (const int*)d_in[3];
    const int*   dst   = (const int*)d_in[4];
    const float* eW1   = (const float*)d_in[5];
    const float* eb1   = (const float*)d_in[6];
    const float* eW2   = (const float*)d_in[7];
    const float* eb2   = (const float*)d_in[8];
    const float* eg    = (const float*)d_in[9];
    const float* ebeta = (const float*)d_in[10];
    const float* nW1   = (const float*)d_in[11];
    const float* nb1   = (const float*)d_in[12];
    const float* nW2   = (const float*)d_in[13];
    const float* nb2   = (const float*)d_in[14];
    const float* ng    = (const float*)d_in[15];
    const float* nbeta = (const float*)d_in[16];
    float* out = (float*)d_out;

    cudaFuncSetAttribute(edge_kernel, cudaFuncAttributeMaxDynamicSharedMemorySize, SMEM_BYTES);
    cudaFuncSetAttribute(node_kernel, cudaFuncAttributeMaxDynamicSharedMemorySize, SMEM_BYTES);

    zero_agg_kernel<<<8192, 1024>>>();
    prep_kernel<<<896, 256>>>(eW1, eW2, nW1, nW2);
    edge_kernel<<<N_EDGE / MT, NTHR, SMEM_BYTES>>>(efeat, gridf, mesh, src, dst,
                                                   eb1, eb2, eg, ebeta);
    node_kernel<<<N_GRID / MT, NTHR, SMEM_BYTES>>>(gridf, nb1, nb2, ng, nbeta, out);
}